// round 2
// baseline (speedup 1.0000x reference)
#include <cuda_runtime.h>

#define NN 50000
#define EE 800000
#define HH 64
#define KIN 128
#define ET (EE + NN)

// ---------------- scratch (static __device__ globals; allocation-free) ------
__device__ __align__(16) float g_h[NN * HH];     // layer projection h
__device__ __align__(16) float g_xp[NN * HH];    // current node features
__device__ __align__(16) float g_agg[NN * HH];   // attention aggregation
__device__ __align__(16) float g_res[NN * HH];   // residual projection
__device__ __align__(16) float g_as[NN];
__device__ __align__(16) float g_ad[NN];
__device__ __align__(16) float g_den[NN];
__device__ __align__(16) float g_ew[ET];
__device__ __align__(16) float g_Wc[KIN * 68];   // conv1 combined weights [128][68]
__device__ __align__(16) float g_Wl[HH * 132];   // layer combined weights [64][132]
__device__ __align__(16) float g_pool[HH];

// ---------------- weight builders -------------------------------------------
// conv1: cols 0..63 = W, 64 = W@a_s, 65 = W@a_d, 66..67 = 0
__global__ void build_w1(const float* __restrict__ W,
                         const float* __restrict__ as_,
                         const float* __restrict__ ad_) {
    int i = blockIdx.x * blockDim.x + threadIdx.x;
    if (i >= KIN * 68) return;
    int k = i / 68, c = i % 68;
    float v = 0.f;
    if (c < 64) {
        v = W[k * 64 + c];
    } else if (c == 64) {
        float s = 0.f;
        #pragma unroll 16
        for (int j = 0; j < 64; j++) s += W[k * 64 + j] * as_[j];
        v = s;
    } else if (c == 65) {
        float s = 0.f;
        #pragma unroll 16
        for (int j = 0; j < 64; j++) s += W[k * 64 + j] * ad_[j];
        v = s;
    }
    g_Wc[i] = v;
}

// layer l: cols 0..63 = convW[l], 64..127 = projW[l], 128 = W@a_s, 129 = W@a_d
__global__ void build_wl(const float* __restrict__ convW,
                         const float* __restrict__ cas,
                         const float* __restrict__ cad,
                         const float* __restrict__ projW, int l) {
    int i = blockIdx.x * blockDim.x + threadIdx.x;
    if (i >= HH * 132) return;
    int k = i / 132, c = i % 132;
    const float* W = convW + l * 64 * 64;
    float v = 0.f;
    if (c < 64) {
        v = W[k * 64 + c];
    } else if (c < 128) {
        v = projW[l * 64 * 64 + k * 64 + (c - 64)];
    } else if (c == 128) {
        float s = 0.f;
        #pragma unroll 16
        for (int j = 0; j < 64; j++) s += W[k * 64 + j] * cas[l * 64 + j];
        v = s;
    } else if (c == 129) {
        float s = 0.f;
        #pragma unroll 16
        for (int j = 0; j < 64; j++) s += W[k * 64 + j] * cad[l * 64 + j];
        v = s;
    }
    g_Wl[i] = v;
}

// ---------------- zero agg + den --------------------------------------------
__global__ void zero_accum() {
    int i = blockIdx.x * blockDim.x + threadIdx.x;   // 3125*256 = 800000
    float4 z = make_float4(0.f, 0.f, 0.f, 0.f);
    ((float4*)g_agg)[i] = z;
    if (i < NN / 4) ((float4*)g_den)[i] = z;
}

// ---------------- conv1 GEMM: A[N,128] x Wc[128,68] -------------------------
__global__ void gemm_conv1(const float* __restrict__ A) {
    __shared__ float Ws[KIN * 68];
    __shared__ float As[16 * KIN];
    int tid = threadIdx.x;
    for (int i = tid; i < KIN * 68; i += 256) Ws[i] = g_Wc[i];
    int base = blockIdx.x * 16 * KIN;
    for (int i = tid; i < 16 * KIN; i += 256) As[i] = A[base + i];
    __syncthreads();
    for (int q = tid; q < 16 * 17; q += 256) {
        int node = q / 17, cq = q % 17;
        const float* a = &As[node * KIN];
        float4 acc = make_float4(0.f, 0.f, 0.f, 0.f);
        #pragma unroll 16
        for (int k = 0; k < KIN; k++) {
            float av = a[k];
            float4 w = *(const float4*)&Ws[k * 68 + cq * 4];
            acc.x += av * w.x; acc.y += av * w.y;
            acc.z += av * w.z; acc.w += av * w.w;
        }
        int n = blockIdx.x * 16 + node;
        int c0 = cq * 4;
        if (c0 < 64) {
            *(float4*)&g_h[n * 64 + c0] = acc;
        } else {
            g_as[n] = acc.x;
            g_ad[n] = acc.y;
        }
    }
}

// ---------------- layer GEMM: g_xp[N,64] x Wl[64,132] -----------------------
__global__ void gemm_layer() {
    __shared__ float Ws[HH * 132];
    __shared__ float As[16 * HH];
    int tid = threadIdx.x;
    for (int i = tid; i < HH * 132; i += 256) Ws[i] = g_Wl[i];
    int base = blockIdx.x * 16 * HH;
    for (int i = tid; i < 16 * HH; i += 256) As[i] = g_xp[base + i];
    __syncthreads();
    for (int q = tid; q < 16 * 33; q += 256) {
        int node = q / 33, cq = q % 33;
        const float* a = &As[node * HH];
        float4 acc = make_float4(0.f, 0.f, 0.f, 0.f);
        #pragma unroll 16
        for (int k = 0; k < HH; k++) {
            float av = a[k];
            float4 w = *(const float4*)&Ws[k * 132 + cq * 4];
            acc.x += av * w.x; acc.y += av * w.y;
            acc.z += av * w.z; acc.w += av * w.w;
        }
        int n = blockIdx.x * 16 + node;
        int c0 = cq * 4;
        if (c0 < 64) {
            *(float4*)&g_h[n * 64 + c0] = acc;
        } else if (c0 < 128) {
            *(float4*)&g_res[n * 64 + (c0 - 64)] = acc;
        } else {
            g_as[n] = acc.x;
            g_ad[n] = acc.y;
        }
    }
}

// ---------------- edge pass A: per-edge softmax weight + denom --------------
// (max-subtraction dropped: alpha = exp(e)/sum exp(e) is algebraically
//  identical and |e| is small enough that exp never overflows)
__global__ void edge_a(const int* __restrict__ ei) {
    int i = blockIdx.x * blockDim.x + threadIdx.x;
    if (i >= ET) return;
    int s, d;
    if (i < EE) { s = ei[i]; d = ei[EE + i]; }
    else        { s = d = i - EE; }
    float e = g_as[s] + g_ad[d];
    e = e > 0.f ? e : 0.2f * e;
    float w = __expf(e);
    g_ew[i] = w;
    atomicAdd(&g_den[d], w);
}

// ---------------- edge pass B: weighted scatter aggregation -----------------
// half-warp per edge; 16 lanes x float4 = 64 features; 128-bit RED atomics
__global__ void edge_b(const int* __restrict__ ei) {
    int t = threadIdx.x;
    int e = blockIdx.x * 16 + (t >> 4);
    if (e >= ET) return;
    int li = t & 15;
    int s, d;
    if (e < EE) { s = ei[e]; d = ei[EE + e]; }
    else        { s = d = e - EE; }
    float alpha = g_ew[e] / (g_den[d] + 1e-16f);
    float4 hv = *(const float4*)&g_h[s * 64 + li * 4];
    float4 v = make_float4(alpha * hv.x, alpha * hv.y, alpha * hv.z, alpha * hv.w);
    atomicAdd((float4*)&g_agg[d * 64 + li * 4], v);   // RED.E.ADD.128 (sm_90+)
}

// ---------------- node epilogues --------------------------------------------
__global__ void node_fin1(const float* __restrict__ b,
                          const float* __restrict__ bg, const float* __restrict__ bb,
                          const float* __restrict__ bm, const float* __restrict__ bv) {
    int i = blockIdx.x * blockDim.x + threadIdx.x;
    if (i >= NN * HH) return;
    int f = i & 63;
    float v = g_agg[i] + b[f];
    v = fmaxf(v, 0.f);
    g_xp[i] = (v - bm[f]) * rsqrtf(bv[f] + 1e-5f) * bg[f] + bb[f];
}

__global__ void node_fin2(const float* __restrict__ cb, const float* __restrict__ pb,
                          const float* __restrict__ bg, const float* __restrict__ bb,
                          const float* __restrict__ bm, const float* __restrict__ bv) {
    int i = blockIdx.x * blockDim.x + threadIdx.x;
    if (i >= NN * HH) return;
    int f = i & 63;
    float v = g_agg[i] + cb[f];
    v = fmaxf(v, 0.f);
    v = (v - bm[f]) * rsqrtf(bv[f] + 1e-5f) * bg[f] + bb[f];
    g_xp[i] = v + g_res[i] + pb[f];
}

// ---------------- pooling + head --------------------------------------------
__global__ void pool_zero() {
    if (threadIdx.x < HH) g_pool[threadIdx.x] = 0.f;
}

__global__ void pool_k() {
    __shared__ float sh[256];
    int t = threadIdx.x;
    int f = t & 63, g = t >> 6;
    float s = 0.f;
    for (int n = blockIdx.x * 4 + g; n < NN; n += 256 * 4)
        s += g_xp[n * 64 + f];
    sh[t] = s;
    __syncthreads();
    if (t < 64) {
        float tot = sh[t] + sh[t + 64] + sh[t + 128] + sh[t + 192];
        atomicAdd(&g_pool[f], tot);
    }
}

__global__ void head_k(const float* __restrict__ hW1, const float* __restrict__ hb1,
                       const float* __restrict__ hg, const float* __restrict__ hb,
                       const float* __restrict__ hm, const float* __restrict__ hv,
                       const float* __restrict__ hW2, const float* __restrict__ hb2,
                       float* __restrict__ out) {
    __shared__ float gs[64];
    __shared__ float hs[32];
    int t = threadIdx.x;
    if (t < 64) gs[t] = g_pool[t] * (1.0f / NN);
    __syncthreads();
    if (t < 32) {
        float acc = hb1[t];
        #pragma unroll 16
        for (int f = 0; f < 64; f++) acc += gs[f] * hW1[f * 32 + t];
        acc = fmaxf(acc, 0.f);
        acc = (acc - hm[t]) * rsqrtf(hv[t] + 1e-5f) * hg[t] + hb[t];
        hs[t] = acc * hW2[t];
    }
    __syncthreads();
    if (t == 0) {
        float s = 0.f;
        for (int j = 0; j < 32; j++) s += hs[j];
        out[0] = s + hb2[0];
    }
}

// ---------------- launch ----------------------------------------------------
extern "C" void kernel_launch(void* const* d_in, const int* in_sizes, int n_in,
                              void* d_out, int out_size) {
    const float* x        = (const float*)d_in[0];
    const int*   ei       = (const int*)d_in[1];
    const float* conv1_W  = (const float*)d_in[2];
    const float* conv1_as = (const float*)d_in[3];
    const float* conv1_ad = (const float*)d_in[4];
    const float* conv1_b  = (const float*)d_in[5];
    const float* convW    = (const float*)d_in[6];
    const float* conv_as  = (const float*)d_in[7];
    const float* conv_ad  = (const float*)d_in[8];
    const float* conv_b   = (const float*)d_in[9];
    const float* bn_g     = (const float*)d_in[10];
    const float* bn_b     = (const float*)d_in[11];
    const float* bn_m     = (const float*)d_in[12];
    const float* bn_v     = (const float*)d_in[13];
    const float* projW    = (const float*)d_in[14];
    const float* projb    = (const float*)d_in[15];
    const float* hW1      = (const float*)d_in[16];
    const float* hb1      = (const float*)d_in[17];
    const float* hbn_g    = (const float*)d_in[18];
    const float* hbn_b    = (const float*)d_in[19];
    const float* hbn_m    = (const float*)d_in[20];
    const float* hbn_v    = (const float*)d_in[21];
    const float* hW2      = (const float*)d_in[22];
    const float* hb2      = (const float*)d_in[23];
    float* out = (float*)d_out;

    const int NB_NODES = NN / 16;                 // 3125
    const int NB_ELEM  = (NN * HH) / 256;         // 12500
    const int NB_EA    = (ET + 255) / 256;
    const int NB_EB    = (ET + 15) / 16;

    // ---- conv1 ----
    build_w1<<<(KIN * 68 + 255) / 256, 256>>>(conv1_W, conv1_as, conv1_ad);
    zero_accum<<<3125, 256>>>();
    gemm_conv1<<<NB_NODES, 256>>>(x);
    edge_a<<<NB_EA, 256>>>(ei);
    edge_b<<<NB_EB, 256>>>(ei);
    node_fin1<<<NB_ELEM, 256>>>(conv1_b, bn_g, bn_b, bn_m, bn_v);

    // ---- conv2..conv5 ----
    for (int l = 0; l < 4; l++) {
        build_wl<<<(HH * 132 + 255) / 256, 256>>>(convW, conv_as, conv_ad, projW, l);
        zero_accum<<<3125, 256>>>();
        gemm_layer<<<NB_NODES, 256>>>();
        edge_a<<<NB_EA, 256>>>(ei);
        edge_b<<<NB_EB, 256>>>(ei);
        node_fin2<<<NB_ELEM, 256>>>(conv_b + l * 64, projb + l * 64,
                                    bn_g + (l + 1) * 64, bn_b + (l + 1) * 64,
                                    bn_m + (l + 1) * 64, bn_v + (l + 1) * 64);
    }

    // ---- pool + head ----
    pool_zero<<<1, 64>>>();
    pool_k<<<256, 256>>>();
    head_k<<<1, 64>>>(hW1, hb1, hbn_g, hbn_b, hbn_m, hbn_v, hW2, hb2, out);
}

// round 4
// speedup vs baseline: 1.2155x; 1.2155x over previous
#include <cuda_runtime.h>

#define NN 50000
#define EE 800000
#define HH 64
#define KIN 128
#define ET (EE + NN)

// ---------------- scratch (static __device__ globals; allocation-free) ------
__device__ __align__(16) float g_h[NN * HH];     // layer projection h
__device__ __align__(16) float g_xp[NN * HH];    // current node features
__device__ __align__(16) float g_res[NN * HH];   // residual projection
__device__ __align__(16) float g_as[NN];
__device__ __align__(16) float g_ad[NN];
__device__ __align__(16) float g_Wc[KIN * 68];   // conv1 combined weights [128][68]
__device__ __align__(16) float g_Wl[HH * 132];   // layer combined weights [64][132]
__device__ __align__(16) float g_pool[HH];

// CSR scratch
__device__ int g_deg[NN + 1];
__device__ int g_rowptr[NN + 1];
__device__ int g_cursor[NN];
__device__ int g_csr_src[ET];

// ---------------- weight builders -------------------------------------------
__global__ void build_w1(const float* __restrict__ W,
                         const float* __restrict__ as_,
                         const float* __restrict__ ad_) {
    int i = blockIdx.x * blockDim.x + threadIdx.x;
    if (i >= KIN * 68) return;
    int k = i / 68, c = i % 68;
    float v = 0.f;
    if (c < 64) {
        v = W[k * 64 + c];
    } else if (c == 64) {
        float s = 0.f;
        #pragma unroll 16
        for (int j = 0; j < 64; j++) s += W[k * 64 + j] * as_[j];
        v = s;
    } else if (c == 65) {
        float s = 0.f;
        #pragma unroll 16
        for (int j = 0; j < 64; j++) s += W[k * 64 + j] * ad_[j];
        v = s;
    }
    g_Wc[i] = v;
}

__global__ void build_wl(const float* __restrict__ convW,
                         const float* __restrict__ cas,
                         const float* __restrict__ cad,
                         const float* __restrict__ projW, int l) {
    int i = blockIdx.x * blockDim.x + threadIdx.x;
    if (i >= HH * 132) return;
    int k = i / 132, c = i % 132;
    const float* W = convW + l * 64 * 64;
    float v = 0.f;
    if (c < 64) {
        v = W[k * 64 + c];
    } else if (c < 128) {
        v = projW[l * 64 * 64 + k * 64 + (c - 64)];
    } else if (c == 128) {
        float s = 0.f;
        #pragma unroll 16
        for (int j = 0; j < 64; j++) s += W[k * 64 + j] * cas[l * 64 + j];
        v = s;
    } else if (c == 129) {
        float s = 0.f;
        #pragma unroll 16
        for (int j = 0; j < 64; j++) s += W[k * 64 + j] * cad[l * 64 + j];
        v = s;
    }
    g_Wl[i] = v;
}

// ---------------- CSR build --------------------------------------------------
__global__ void deg_init() {
    int i = blockIdx.x * blockDim.x + threadIdx.x;
    if (i <= NN) g_deg[i] = (i < NN) ? 1 : 0;   // self-loop counted up front
}

__global__ void deg_count(const int* __restrict__ ei) {
    int i = blockIdx.x * blockDim.x + threadIdx.x;
    if (i >= EE) return;
    atomicAdd(&g_deg[ei[EE + i]], 1);
}

// single-block exclusive scan over g_deg[0..NN] -> g_rowptr
__global__ void scan_k() {
    __shared__ int part[1024];
    const int CH = 49;                           // 1024*49 = 50176 >= 50001
    int t = threadIdx.x;
    int base = t * CH;
    int vals[CH];
    int s = 0;
    #pragma unroll
    for (int i = 0; i < CH; i++) {
        int idx = base + i;
        int v = (idx < NN) ? g_deg[idx] : 0;
        vals[i] = s;                             // exclusive within chunk
        s += v;
    }
    part[t] = s;
    __syncthreads();
    // Hillis-Steele inclusive scan of per-thread totals
    for (int off = 1; off < 1024; off <<= 1) {
        int v = (t >= off) ? part[t - off] : 0;
        __syncthreads();
        part[t] += v;
        __syncthreads();
    }
    int prev = (t == 0) ? 0 : part[t - 1];
    #pragma unroll
    for (int i = 0; i < CH; i++) {
        int idx = base + i;
        if (idx <= NN) g_rowptr[idx] = prev + vals[i];
    }
}

__global__ void cursor_init() {
    int n = blockIdx.x * blockDim.x + threadIdx.x;
    if (n >= NN) return;
    int r = g_rowptr[n];
    g_csr_src[r] = n;                            // self loop first
    g_cursor[n] = r + 1;
}

__global__ void csr_fill(const int* __restrict__ ei) {
    int i = blockIdx.x * blockDim.x + threadIdx.x;
    if (i >= EE) return;
    int s = ei[i], d = ei[EE + i];
    int pos = atomicAdd(&g_cursor[d], 1);
    g_csr_src[pos] = s;
}

// ---------------- conv1 GEMM: A[N,128] x Wc[128,68] -------------------------
__global__ void gemm_conv1(const float* __restrict__ A) {
    __shared__ float Ws[KIN * 68];
    __shared__ float As[16 * KIN];
    int tid = threadIdx.x;
    for (int i = tid; i < KIN * 68; i += 256) Ws[i] = g_Wc[i];
    int base = blockIdx.x * 16 * KIN;
    for (int i = tid; i < 16 * KIN; i += 256) As[i] = A[base + i];
    __syncthreads();
    for (int q = tid; q < 16 * 17; q += 256) {
        int node = q / 17, cq = q % 17;
        const float* a = &As[node * KIN];
        float4 acc = make_float4(0.f, 0.f, 0.f, 0.f);
        #pragma unroll 16
        for (int k = 0; k < KIN; k++) {
            float av = a[k];
            float4 w = *(const float4*)&Ws[k * 68 + cq * 4];
            acc.x += av * w.x; acc.y += av * w.y;
            acc.z += av * w.z; acc.w += av * w.w;
        }
        int n = blockIdx.x * 16 + node;
        int c0 = cq * 4;
        if (c0 < 64) {
            *(float4*)&g_h[n * 64 + c0] = acc;
        } else {
            g_as[n] = acc.x;
            g_ad[n] = acc.y;
        }
    }
}

// ---------------- layer GEMM: g_xp[N,64] x Wl[64,132] -----------------------
__global__ void gemm_layer() {
    __shared__ float Ws[HH * 132];
    __shared__ float As[16 * HH];
    int tid = threadIdx.x;
    for (int i = tid; i < HH * 132; i += 256) Ws[i] = g_Wl[i];
    int base = blockIdx.x * 16 * HH;
    for (int i = tid; i < 16 * HH; i += 256) As[i] = g_xp[base + i];
    __syncthreads();
    for (int q = tid; q < 16 * 33; q += 256) {
        int node = q / 33, cq = q % 33;
        const float* a = &As[node * HH];
        float4 acc = make_float4(0.f, 0.f, 0.f, 0.f);
        #pragma unroll 16
        for (int k = 0; k < HH; k++) {
            float av = a[k];
            float4 w = *(const float4*)&Ws[k * 132 + cq * 4];
            acc.x += av * w.x; acc.y += av * w.y;
            acc.z += av * w.z; acc.w += av * w.w;
        }
        int n = blockIdx.x * 16 + node;
        int c0 = cq * 4;
        if (c0 < 64) {
            *(float4*)&g_h[n * 64 + c0] = acc;
        } else if (c0 < 128) {
            *(float4*)&g_res[n * 64 + (c0 - 64)] = acc;
        } else {
            g_as[n] = acc.x;
            g_ad[n] = acc.y;
        }
    }
}

// ---------------- fused GAT aggregation + epilogue ---------------------------
// One warp per destination node. Pass 1: softmax denominator (warp-strided).
// Pass 2: serial edge walk; each lane owns 2 features (coalesced 256B rows).
// Softmax max-subtraction dropped (algebraically identical, |e| small).
template <int FIRST>
__global__ void gat_agg(const float* __restrict__ cb,
                        const float* __restrict__ pb,
                        const float* __restrict__ bg, const float* __restrict__ bb,
                        const float* __restrict__ bm, const float* __restrict__ bv) {
    int warp = (blockIdx.x * blockDim.x + threadIdx.x) >> 5;
    if (warp >= NN) return;
    int lane = threadIdx.x & 31;
    int beg = g_rowptr[warp];
    int end = g_rowptr[warp + 1];
    float adv = g_ad[warp];

    // pass 1: denominator
    float s = 0.f;
    for (int j = beg + lane; j < end; j += 32) {
        int src = g_csr_src[j];
        float e = g_as[src] + adv;
        e = e > 0.f ? e : 0.2f * e;
        s += __expf(e);
    }
    #pragma unroll
    for (int off = 16; off > 0; off >>= 1)
        s += __shfl_xor_sync(0xffffffffu, s, off);
    float inv = 1.f / (s + 1e-16f);

    // pass 2: weighted accumulation (software-pipelined src prefetch)
    float2 acc = make_float2(0.f, 0.f);
    int src = g_csr_src[beg];
    float asv = g_as[src];
    for (int j = beg; j < end; j++) {
        int csrc = src;
        float cas_ = asv;
        if (j + 1 < end) {
            src = g_csr_src[j + 1];
            asv = g_as[src];
        }
        float e = cas_ + adv;
        e = e > 0.f ? e : 0.2f * e;
        float w = __expf(e);
        float2 hv = *(const float2*)&g_h[csrc * 64 + lane * 2];
        acc.x += w * hv.x;
        acc.y += w * hv.y;
    }
    acc.x *= inv;
    acc.y *= inv;

    // epilogue: bias -> relu -> bn (-> + residual)
    int f = lane * 2;
    float v0 = fmaxf(acc.x + cb[f],     0.f);
    float v1 = fmaxf(acc.y + cb[f + 1], 0.f);
    v0 = (v0 - bm[f])     * rsqrtf(bv[f]     + 1e-5f) * bg[f]     + bb[f];
    v1 = (v1 - bm[f + 1]) * rsqrtf(bv[f + 1] + 1e-5f) * bg[f + 1] + bb[f + 1];
    if (!FIRST) {
        float2 rv = *(const float2*)&g_res[warp * 64 + f];
        v0 += rv.x + pb[f];
        v1 += rv.y + pb[f + 1];
    }
    float2 o = make_float2(v0, v1);
    *(float2*)&g_xp[warp * 64 + f] = o;
}

// ---------------- pooling + head --------------------------------------------
__global__ void pool_zero() {
    if (threadIdx.x < HH) g_pool[threadIdx.x] = 0.f;
}

__global__ void pool_k() {
    __shared__ float sh[256];
    int t = threadIdx.x;
    int f = t & 63, g = t >> 6;
    float s = 0.f;
    for (int n = blockIdx.x * 4 + g; n < NN; n += 256 * 4)
        s += g_xp[n * 64 + f];
    sh[t] = s;
    __syncthreads();
    if (t < 64) {
        float tot = sh[t] + sh[t + 64] + sh[t + 128] + sh[t + 192];
        atomicAdd(&g_pool[f], tot);
    }
}

__global__ void head_k(const float* __restrict__ hW1, const float* __restrict__ hb1,
                       const float* __restrict__ hg, const float* __restrict__ hb,
                       const float* __restrict__ hm, const float* __restrict__ hv,
                       const float* __restrict__ hW2, const float* __restrict__ hb2,
                       float* __restrict__ out) {
    __shared__ float gs[64];
    __shared__ float hs[32];
    int t = threadIdx.x;
    if (t < 64) gs[t] = g_pool[t] * (1.0f / NN);
    __syncthreads();
    if (t < 32) {
        float acc = hb1[t];
        #pragma unroll 16
        for (int f = 0; f < 64; f++) acc += gs[f] * hW1[f * 32 + t];
        acc = fmaxf(acc, 0.f);
        acc = (acc - hm[t]) * rsqrtf(hv[t] + 1e-5f) * hg[t] + hb[t];
        hs[t] = acc * hW2[t];
    }
    __syncthreads();
    if (t == 0) {
        float s = 0.f;
        for (int j = 0; j < 32; j++) s += hs[j];
        out[0] = s + hb2[0];
    }
}

// ---------------- launch ----------------------------------------------------
extern "C" void kernel_launch(void* const* d_in, const int* in_sizes, int n_in,
                              void* d_out, int out_size) {
    const float* x        = (const float*)d_in[0];
    const int*   ei       = (const int*)d_in[1];
    const float* conv1_W  = (const float*)d_in[2];
    const float* conv1_as = (const float*)d_in[3];
    const float* conv1_ad = (const float*)d_in[4];
    const float* conv1_b  = (const float*)d_in[5];
    const float* convW    = (const float*)d_in[6];
    const float* conv_as  = (const float*)d_in[7];
    const float* conv_ad  = (const float*)d_in[8];
    const float* conv_b   = (const float*)d_in[9];
    const float* bn_g     = (const float*)d_in[10];
    const float* bn_b     = (const float*)d_in[11];
    const float* bn_m     = (const float*)d_in[12];
    const float* bn_v     = (const float*)d_in[13];
    const float* projW    = (const float*)d_in[14];
    const float* projb    = (const float*)d_in[15];
    const float* hW1      = (const float*)d_in[16];
    const float* hb1      = (const float*)d_in[17];
    const float* hbn_g    = (const float*)d_in[18];
    const float* hbn_b    = (const float*)d_in[19];
    const float* hbn_m    = (const float*)d_in[20];
    const float* hbn_v    = (const float*)d_in[21];
    const float* hW2      = (const float*)d_in[22];
    const float* hb2      = (const float*)d_in[23];
    float* out = (float*)d_out;

    const int NB_NODES = NN / 16;                       // 3125
    const int NB_E     = (EE + 255) / 256;              // 3125
    const int NB_AGG   = (NN * 32 + 255) / 256;         // 6250 (warp per node)

    // ---- CSR build (once per launch, reused by all 5 layers) ----
    deg_init<<<(NN + 256) / 256, 256>>>();
    deg_count<<<NB_E, 256>>>(ei);
    scan_k<<<1, 1024>>>();
    cursor_init<<<(NN + 255) / 256, 256>>>();
    csr_fill<<<NB_E, 256>>>(ei);

    // ---- conv1 ----
    build_w1<<<(KIN * 68 + 255) / 256, 256>>>(conv1_W, conv1_as, conv1_ad);
    gemm_conv1<<<NB_NODES, 256>>>(x);
    gat_agg<1><<<NB_AGG, 256>>>(conv1_b, nullptr, bn_g, bn_b, bn_m, bn_v);

    // ---- conv2..conv5 ----
    for (int l = 0; l < 4; l++) {
        build_wl<<<(HH * 132 + 255) / 256, 256>>>(convW, conv_as, conv_ad, projW, l);
        gemm_layer<<<NB_NODES, 256>>>();
        gat_agg<0><<<NB_AGG, 256>>>(conv_b + l * 64, projb + l * 64,
                                    bn_g + (l + 1) * 64, bn_b + (l + 1) * 64,
                                    bn_m + (l + 1) * 64, bn_v + (l + 1) * 64);
    }

    // ---- pool + head ----
    pool_zero<<<1, 64>>>();
    pool_k<<<256, 256>>>();
    head_k<<<1, 64>>>(hW1, hb1, hbn_g, hbn_b, hbn_m, hbn_v, hW2, hb2, out);
}

// round 5
// speedup vs baseline: 1.8328x; 1.5079x over previous
#include <cuda_runtime.h>

#define NN 50000
#define EE 800000
#define HH 64
#define KIN 128
#define ET (EE + NN)

// ---------------- scratch (static __device__ globals; allocation-free) ------
__device__ __align__(16) float g_h[NN * HH];     // layer projection h
__device__ __align__(16) float g_xp[NN * HH];    // current node features
__device__ __align__(16) float g_res[NN * HH];   // residual projection
__device__ __align__(16) float g_as[NN];
__device__ __align__(16) float g_ad[NN];
__device__ __align__(16) float g_pool[HH];

// CSR scratch
__device__ int g_deg[NN + 1];
__device__ int g_rowptr[NN + 1];
__device__ int g_cursor[NN];
__device__ int g_csr_src[ET];

// ---------------- f32x2 packed helpers (sm_103a) -----------------------------
typedef unsigned long long ull;

__device__ __forceinline__ void ffma2(ull& d, ull a, ull b) {
    asm("fma.rn.f32x2 %0, %1, %2, %0;" : "+l"(d) : "l"(a), "l"(b));
}
__device__ __forceinline__ ull pack2(float x) {
    ull r; unsigned u = __float_as_uint(x);
    asm("mov.b64 %0, {%1, %2};" : "=l"(r) : "r"(u), "r"(u));
    return r;
}
__device__ __forceinline__ void unpack2(ull v, float& lo, float& hi) {
    unsigned a, b;
    asm("mov.b64 {%0, %1}, %2;" : "=r"(a), "=r"(b) : "l"(v));
    lo = __uint_as_float(a); hi = __uint_as_float(b);
}

// ---------------- CSR build --------------------------------------------------
__global__ void deg_init() {
    int i = blockIdx.x * blockDim.x + threadIdx.x;
    if (i <= NN) g_deg[i] = (i < NN) ? 1 : 0;   // self-loop counted up front
}

__global__ void deg_count(const int* __restrict__ ei) {
    int i = blockIdx.x * blockDim.x + threadIdx.x;
    if (i >= EE) return;
    atomicAdd(&g_deg[ei[EE + i]], 1);
}

__global__ void scan_k() {
    __shared__ int part[1024];
    const int CH = 49;
    int t = threadIdx.x;
    int base = t * CH;
    int vals[CH];
    int s = 0;
    #pragma unroll
    for (int i = 0; i < CH; i++) {
        int idx = base + i;
        int v = (idx < NN) ? g_deg[idx] : 0;
        vals[i] = s;
        s += v;
    }
    part[t] = s;
    __syncthreads();
    for (int off = 1; off < 1024; off <<= 1) {
        int v = (t >= off) ? part[t - off] : 0;
        __syncthreads();
        part[t] += v;
        __syncthreads();
    }
    int prev = (t == 0) ? 0 : part[t - 1];
    #pragma unroll
    for (int i = 0; i < CH; i++) {
        int idx = base + i;
        if (idx <= NN) g_rowptr[idx] = prev + vals[i];
    }
}

__global__ void cursor_init() {
    int n = blockIdx.x * blockDim.x + threadIdx.x;
    if (n >= NN) return;
    int r = g_rowptr[n];
    g_csr_src[r] = n;                            // self loop first
    g_cursor[n] = r + 1;
}

__global__ void csr_fill(const int* __restrict__ ei) {
    int i = blockIdx.x * blockDim.x + threadIdx.x;
    if (i >= EE) return;
    int s = ei[i], d = ei[EE + i];
    int pos = atomicAdd(&g_cursor[d], 1);
    g_csr_src[pos] = s;
}

// ---------------- conv1 GEMM: x[N,128] x W[128,64] -> g_h --------------------
// 64 nodes/block, 128 threads (tx=16 colgroups, ty=8 -> 4 node-pairs each).
// Packed f32x2: accumulator pair = (node0, node1) for one column.
__global__ void gemm_conv1(const float* __restrict__ A,
                           const float* __restrict__ W) {
    extern __shared__ float sm[];
    float* Ws  = sm;                 // [128][64]
    float* Ast = sm + KIN * 64;      // [128][66]  (transposed A, pad 66)
    const int AST = 66;

    int tid = threadIdx.x;
    int tx = tid & 15;               // colgroup (4 cols)
    int ty = tid >> 4;               // 0..7

    for (int i = tid; i < KIN * 64; i += 128) Ws[i] = W[i];
    int nbase = blockIdx.x * 64;
    for (int i = tid; i < 64 * KIN; i += 128) {
        int node = i / KIN, k = i % KIN;
        int n = nbase + node;
        Ast[k * AST + node] = (n < NN) ? A[n * KIN + k] : 0.f;
    }
    __syncthreads();

    ull acc[4][4];
    #pragma unroll
    for (int p = 0; p < 4; p++)
        #pragma unroll
        for (int c = 0; c < 4; c++) acc[p][c] = 0ull;

    #pragma unroll 4
    for (int k = 0; k < KIN; k++) {
        float4 wv = *(const float4*)&Ws[k * 64 + tx * 4];
        ull w0 = pack2(wv.x), w1 = pack2(wv.y), w2 = pack2(wv.z), w3 = pack2(wv.w);
        #pragma unroll
        for (int p = 0; p < 4; p++) {
            int pair = ty + 8 * p;
            ull ap = *(const ull*)&Ast[k * AST + 2 * pair];
            ffma2(acc[p][0], ap, w0);
            ffma2(acc[p][1], ap, w1);
            ffma2(acc[p][2], ap, w2);
            ffma2(acc[p][3], ap, w3);
        }
    }

    #pragma unroll
    for (int p = 0; p < 4; p++) {
        int n0 = nbase + 2 * (ty + 8 * p);
        if (n0 >= NN) continue;
        bool ok1 = (n0 + 1) < NN;
        #pragma unroll
        for (int c = 0; c < 4; c++) {
            float v0, v1;
            unpack2(acc[p][c], v0, v1);
            int col = tx * 4 + c;
            g_h[n0 * 64 + col] = v0;
            if (ok1) g_h[(n0 + 1) * 64 + col] = v1;
        }
    }
}

// ---------------- layer GEMM: g_xp[N,64] x [convW|projW][64,128] -------------
// 64 nodes/block, 256 threads (tx=32 colgroups, ty=8 -> 4 node-pairs each).
__global__ void gemm_layer(const float* __restrict__ CW,
                           const float* __restrict__ PW) {
    extern __shared__ float sm[];
    float* Ws  = sm;                 // [64][128]: cols 0..63 conv, 64..127 proj
    float* Ast = sm + HH * 128;      // [64][66]
    const int AST = 66;

    int tid = threadIdx.x;
    int tx = tid & 31;
    int ty = tid >> 5;

    for (int i = tid; i < HH * 128; i += 256) {
        int k = i >> 7, c = i & 127;
        Ws[i] = (c < 64) ? CW[k * 64 + c] : PW[k * 64 + (c - 64)];
    }
    int nbase = blockIdx.x * 64;
    for (int i = tid; i < 64 * HH; i += 256) {
        int node = i >> 6, k = i & 63;
        int n = nbase + node;
        Ast[k * AST + node] = (n < NN) ? g_xp[n * 64 + k] : 0.f;
    }
    __syncthreads();

    ull acc[4][4];
    #pragma unroll
    for (int p = 0; p < 4; p++)
        #pragma unroll
        for (int c = 0; c < 4; c++) acc[p][c] = 0ull;

    #pragma unroll 4
    for (int k = 0; k < HH; k++) {
        float4 wv = *(const float4*)&Ws[k * 128 + tx * 4];
        ull w0 = pack2(wv.x), w1 = pack2(wv.y), w2 = pack2(wv.z), w3 = pack2(wv.w);
        #pragma unroll
        for (int p = 0; p < 4; p++) {
            int pair = ty + 8 * p;
            ull ap = *(const ull*)&Ast[k * AST + 2 * pair];
            ffma2(acc[p][0], ap, w0);
            ffma2(acc[p][1], ap, w1);
            ffma2(acc[p][2], ap, w2);
            ffma2(acc[p][3], ap, w3);
        }
    }

    #pragma unroll
    for (int p = 0; p < 4; p++) {
        int n0 = nbase + 2 * (ty + 8 * p);
        if (n0 >= NN) continue;
        bool ok1 = (n0 + 1) < NN;
        #pragma unroll
        for (int c = 0; c < 4; c++) {
            float v0, v1;
            unpack2(acc[p][c], v0, v1);
            int col = tx * 4 + c;
            float* dst = (col < 64) ? &g_h[0] + n0 * 64 + col
                                    : &g_res[0] + n0 * 64 + (col - 64);
            dst[0] = v0;
            if (ok1) dst[64] = v1;
        }
    }
}

// ---------------- attention projections: as/ad = h @ a ----------------------
__global__ void attn_proj(const float* __restrict__ av,
                          const float* __restrict__ adv) {
    int warp = (blockIdx.x * blockDim.x + threadIdx.x) >> 5;
    if (warp >= NN) return;
    int lane = threadIdx.x & 31;
    float h0 = g_h[warp * 64 + lane];
    float h1 = g_h[warp * 64 + 32 + lane];
    float sa = h0 * av[lane]  + h1 * av[lane + 32];
    float sd = h0 * adv[lane] + h1 * adv[lane + 32];
    #pragma unroll
    for (int off = 16; off > 0; off >>= 1) {
        sa += __shfl_xor_sync(0xffffffffu, sa, off);
        sd += __shfl_xor_sync(0xffffffffu, sd, off);
    }
    if (lane == 0) {
        g_as[warp] = sa;
        g_ad[warp] = sd;
    }
}

// ---------------- fused GAT aggregation + epilogue (single pass) -------------
// One warp per destination node; denominator and weighted sum in one walk.
template <int FIRST>
__global__ void gat_agg(const float* __restrict__ cb,
                        const float* __restrict__ pb,
                        const float* __restrict__ bg, const float* __restrict__ bb,
                        const float* __restrict__ bm, const float* __restrict__ bv) {
    int warp = (blockIdx.x * blockDim.x + threadIdx.x) >> 5;
    if (warp >= NN) return;
    int lane = threadIdx.x & 31;
    int beg = g_rowptr[warp];
    int end = g_rowptr[warp + 1];
    float adv = g_ad[warp];

    float s = 0.f;
    float2 acc = make_float2(0.f, 0.f);
    int src = g_csr_src[beg];
    float asv = g_as[src];
    for (int j = beg; j < end; j++) {
        int csrc = src;
        float cas_ = asv;
        if (j + 1 < end) {
            src = g_csr_src[j + 1];
            asv = g_as[src];
        }
        float e = cas_ + adv;
        e = e > 0.f ? e : 0.2f * e;
        float w = __expf(e);
        s += w;
        float2 hv = *(const float2*)&g_h[csrc * 64 + lane * 2];
        acc.x += w * hv.x;
        acc.y += w * hv.y;
    }
    float inv = 1.f / (s + 1e-16f);
    acc.x *= inv;
    acc.y *= inv;

    int f = lane * 2;
    float v0 = fmaxf(acc.x + cb[f],     0.f);
    float v1 = fmaxf(acc.y + cb[f + 1], 0.f);
    v0 = (v0 - bm[f])     * rsqrtf(bv[f]     + 1e-5f) * bg[f]     + bb[f];
    v1 = (v1 - bm[f + 1]) * rsqrtf(bv[f + 1] + 1e-5f) * bg[f + 1] + bb[f + 1];
    if (!FIRST) {
        float2 rv = *(const float2*)&g_res[warp * 64 + f];
        v0 += rv.x + pb[f];
        v1 += rv.y + pb[f + 1];
    }
    *(float2*)&g_xp[warp * 64 + f] = make_float2(v0, v1);
}

// ---------------- pooling + head --------------------------------------------
__global__ void pool_zero() {
    if (threadIdx.x < HH) g_pool[threadIdx.x] = 0.f;
}

__global__ void pool_k() {
    __shared__ float sh[256];
    int t = threadIdx.x;
    int f = t & 63, g = t >> 6;
    float s = 0.f;
    for (int n = blockIdx.x * 4 + g; n < NN; n += 256 * 4)
        s += g_xp[n * 64 + f];
    sh[t] = s;
    __syncthreads();
    if (t < 64) {
        float tot = sh[t] + sh[t + 64] + sh[t + 128] + sh[t + 192];
        atomicAdd(&g_pool[f], tot);
    }
}

__global__ void head_k(const float* __restrict__ hW1, const float* __restrict__ hb1,
                       const float* __restrict__ hg, const float* __restrict__ hb,
                       const float* __restrict__ hm, const float* __restrict__ hv,
                       const float* __restrict__ hW2, const float* __restrict__ hb2,
                       float* __restrict__ out) {
    __shared__ float gs[64];
    __shared__ float hs[32];
    int t = threadIdx.x;
    if (t < 64) gs[t] = g_pool[t] * (1.0f / NN);
    __syncthreads();
    if (t < 32) {
        float acc = hb1[t];
        #pragma unroll 16
        for (int f = 0; f < 64; f++) acc += gs[f] * hW1[f * 32 + t];
        acc = fmaxf(acc, 0.f);
        acc = (acc - hm[t]) * rsqrtf(hv[t] + 1e-5f) * hg[t] + hb[t];
        hs[t] = acc * hW2[t];
    }
    __syncthreads();
    if (t == 0) {
        float s = 0.f;
        for (int j = 0; j < 32; j++) s += hs[j];
        out[0] = s + hb2[0];
    }
}

// ---------------- launch ----------------------------------------------------
extern "C" void kernel_launch(void* const* d_in, const int* in_sizes, int n_in,
                              void* d_out, int out_size) {
    const float* x        = (const float*)d_in[0];
    const int*   ei       = (const int*)d_in[1];
    const float* conv1_W  = (const float*)d_in[2];
    const float* conv1_as = (const float*)d_in[3];
    const float* conv1_ad = (const float*)d_in[4];
    const float* conv1_b  = (const float*)d_in[5];
    const float* convW    = (const float*)d_in[6];
    const float* conv_as  = (const float*)d_in[7];
    const float* conv_ad  = (const float*)d_in[8];
    const float* conv_b   = (const float*)d_in[9];
    const float* bn_g     = (const float*)d_in[10];
    const float* bn_b     = (const float*)d_in[11];
    const float* bn_m     = (const float*)d_in[12];
    const float* bn_v     = (const float*)d_in[13];
    const float* projW    = (const float*)d_in[14];
    const float* projb    = (const float*)d_in[15];
    const float* hW1      = (const float*)d_in[16];
    const float* hb1      = (const float*)d_in[17];
    const float* hbn_g    = (const float*)d_in[18];
    const float* hbn_b    = (const float*)d_in[19];
    const float* hbn_m    = (const float*)d_in[20];
    const float* hbn_v    = (const float*)d_in[21];
    const float* hW2      = (const float*)d_in[22];
    const float* hb2      = (const float*)d_in[23];
    float* out = (float*)d_out;

    const int NB_E    = (EE + 255) / 256;               // 3125
    const int NB_GEMM = (NN + 63) / 64;                 // 782
    const int NB_WARP = (NN * 32 + 255) / 256;          // 6250 (warp per node)

    const int SMEM_C1 = (KIN * 64 + KIN * 66) * 4;      // 66560 B
    const int SMEM_L  = (HH * 128 + HH * 66) * 4;       // 49664 B
    static int smem_set = 0;
    if (!smem_set) {
        cudaFuncSetAttribute(gemm_conv1, cudaFuncAttributeMaxDynamicSharedMemorySize, SMEM_C1);
        cudaFuncSetAttribute(gemm_layer, cudaFuncAttributeMaxDynamicSharedMemorySize, SMEM_L);
        smem_set = 1;
    }

    // ---- CSR build (once per launch, reused by all 5 layers) ----
    deg_init<<<(NN + 256) / 256, 256>>>();
    deg_count<<<NB_E, 256>>>(ei);
    scan_k<<<1, 1024>>>();
    cursor_init<<<(NN + 255) / 256, 256>>>();
    csr_fill<<<NB_E, 256>>>(ei);

    // ---- conv1 ----
    gemm_conv1<<<NB_GEMM, 128, SMEM_C1>>>(x, conv1_W);
    attn_proj<<<NB_WARP, 256>>>(conv1_as, conv1_ad);
    gat_agg<1><<<NB_WARP, 256>>>(conv1_b, nullptr, bn_g, bn_b, bn_m, bn_v);

    // ---- conv2..conv5 ----
    for (int l = 0; l < 4; l++) {
        gemm_layer<<<NB_GEMM, 256, SMEM_L>>>(convW + l * 4096, projW + l * 4096);
        attn_proj<<<NB_WARP, 256>>>(conv_as + l * 64, conv_ad + l * 64);
        gat_agg<0><<<NB_WARP, 256>>>(conv_b + l * 64, projb + l * 64,
                                     bn_g + (l + 1) * 64, bn_b + (l + 1) * 64,
                                     bn_m + (l + 1) * 64, bn_v + (l + 1) * 64);
    }

    // ---- pool + head ----
    pool_zero<<<1, 64>>>();
    pool_k<<<256, 256>>>();
    head_k<<<1, 64>>>(hW1, hb1, hbn_g, hbn_b, hbn_m, hbn_v, hW2, hb2, out);
}

// round 6
// speedup vs baseline: 1.9667x; 1.0730x over previous
#include <cuda_runtime.h>

#define NN 50000
#define EE 800000
#define HH 64
#define KIN 128
#define ET (EE + NN)

// ---------------- scratch (static __device__ globals; allocation-free) ------
__device__ __align__(16) float g_h[NN * HH];     // layer projection h
__device__ __align__(16) float g_xp[NN * HH];    // current node features
__device__ __align__(16) float g_res[NN * HH];   // residual projection
__device__ __align__(16) float g_as[NN];
__device__ __align__(16) float g_ad[NN];
__device__ __align__(16) float g_pool[HH];

// CSR scratch
__device__ int g_deg[NN + 1];
__device__ int g_rowptr[NN + 1];
__device__ int g_cursor[NN];
__device__ int g_csr_src[ET];
__device__ int g_csr_dst[ET];
__device__ float g_ew[ET];

// ---------------- f32x2 packed helpers (sm_103a) -----------------------------
typedef unsigned long long ull;

__device__ __forceinline__ void ffma2(ull& d, ull a, ull b) {
    asm("fma.rn.f32x2 %0, %1, %2, %0;" : "+l"(d) : "l"(a), "l"(b));
}
__device__ __forceinline__ ull pack2(float x) {
    ull r; unsigned u = __float_as_uint(x);
    asm("mov.b64 %0, {%1, %2};" : "=l"(r) : "r"(u), "r"(u));
    return r;
}
__device__ __forceinline__ void unpack2(ull v, float& lo, float& hi) {
    unsigned a, b;
    asm("mov.b64 {%0, %1}, %2;" : "=r"(a), "=r"(b) : "l"(v));
    lo = __uint_as_float(a); hi = __uint_as_float(b);
}

// ---------------- CSR build --------------------------------------------------
__global__ void deg_init() {
    int i = blockIdx.x * blockDim.x + threadIdx.x;
    if (i <= NN) g_deg[i] = (i < NN) ? 1 : 0;   // self-loop counted up front
}

__global__ void deg_count(const int* __restrict__ ei) {
    int i = blockIdx.x * blockDim.x + threadIdx.x;
    if (i >= EE) return;
    atomicAdd(&g_deg[ei[EE + i]], 1);
}

__global__ void scan_k() {
    __shared__ int part[1024];
    const int CH = 49;
    int t = threadIdx.x;
    int base = t * CH;
    int vals[CH];
    int s = 0;
    #pragma unroll
    for (int i = 0; i < CH; i++) {
        int idx = base + i;
        int v = (idx < NN) ? g_deg[idx] : 0;
        vals[i] = s;
        s += v;
    }
    part[t] = s;
    __syncthreads();
    for (int off = 1; off < 1024; off <<= 1) {
        int v = (t >= off) ? part[t - off] : 0;
        __syncthreads();
        part[t] += v;
        __syncthreads();
    }
    int prev = (t == 0) ? 0 : part[t - 1];
    #pragma unroll
    for (int i = 0; i < CH; i++) {
        int idx = base + i;
        if (idx <= NN) g_rowptr[idx] = prev + vals[i];
    }
}

__global__ void cursor_init() {
    int n = blockIdx.x * blockDim.x + threadIdx.x;
    if (n >= NN) return;
    int r = g_rowptr[n];
    g_csr_src[r] = n;                            // self loop first
    g_csr_dst[r] = n;
    g_cursor[n] = r + 1;
}

__global__ void csr_fill(const int* __restrict__ ei) {
    int i = blockIdx.x * blockDim.x + threadIdx.x;
    if (i >= EE) return;
    int s = ei[i], d = ei[EE + i];
    int pos = atomicAdd(&g_cursor[d], 1);
    g_csr_src[pos] = s;
    g_csr_dst[pos] = d;
}

// ---------------- conv1 GEMM: x[N,128] x W[128,64] -> g_h --------------------
__global__ void gemm_conv1(const float* __restrict__ A,
                           const float* __restrict__ W) {
    extern __shared__ float sm[];
    float* Ws  = sm;                 // [128][64]
    float* Ast = sm + KIN * 64;      // [128][66]
    const int AST = 66;

    int tid = threadIdx.x;
    int tx = tid & 15;
    int ty = tid >> 4;

    for (int i = tid; i < KIN * 64; i += 128) Ws[i] = W[i];
    int nbase = blockIdx.x * 64;
    for (int i = tid; i < 64 * KIN; i += 128) {
        int node = i / KIN, k = i % KIN;
        int n = nbase + node;
        Ast[k * AST + node] = (n < NN) ? A[n * KIN + k] : 0.f;
    }
    __syncthreads();

    ull acc[4][4];
    #pragma unroll
    for (int p = 0; p < 4; p++)
        #pragma unroll
        for (int c = 0; c < 4; c++) acc[p][c] = 0ull;

    #pragma unroll 4
    for (int k = 0; k < KIN; k++) {
        float4 wv = *(const float4*)&Ws[k * 64 + tx * 4];
        ull w0 = pack2(wv.x), w1 = pack2(wv.y), w2 = pack2(wv.z), w3 = pack2(wv.w);
        #pragma unroll
        for (int p = 0; p < 4; p++) {
            int pair = ty + 8 * p;
            ull ap = *(const ull*)&Ast[k * AST + 2 * pair];
            ffma2(acc[p][0], ap, w0);
            ffma2(acc[p][1], ap, w1);
            ffma2(acc[p][2], ap, w2);
            ffma2(acc[p][3], ap, w3);
        }
    }

    #pragma unroll
    for (int p = 0; p < 4; p++) {
        int n0 = nbase + 2 * (ty + 8 * p);
        if (n0 >= NN) continue;
        bool ok1 = (n0 + 1) < NN;
        #pragma unroll
        for (int c = 0; c < 4; c++) {
            float v0, v1;
            unpack2(acc[p][c], v0, v1);
            int col = tx * 4 + c;
            g_h[n0 * 64 + col] = v0;
            if (ok1) g_h[(n0 + 1) * 64 + col] = v1;
        }
    }
}

// ---------------- layer GEMM: g_xp[N,64] x [convW|projW][64,128] -------------
__global__ void gemm_layer(const float* __restrict__ CW,
                           const float* __restrict__ PW) {
    extern __shared__ float sm[];
    float* Ws  = sm;                 // [64][128]
    float* Ast = sm + HH * 128;      // [64][66]
    const int AST = 66;

    int tid = threadIdx.x;
    int tx = tid & 31;
    int ty = tid >> 5;

    for (int i = tid; i < HH * 128; i += 256) {
        int k = i >> 7, c = i & 127;
        Ws[i] = (c < 64) ? CW[k * 64 + c] : PW[k * 64 + (c - 64)];
    }
    int nbase = blockIdx.x * 64;
    for (int i = tid; i < 64 * HH; i += 256) {
        int node = i >> 6, k = i & 63;
        int n = nbase + node;
        Ast[k * AST + node] = (n < NN) ? g_xp[n * 64 + k] : 0.f;
    }
    __syncthreads();

    ull acc[4][4];
    #pragma unroll
    for (int p = 0; p < 4; p++)
        #pragma unroll
        for (int c = 0; c < 4; c++) acc[p][c] = 0ull;

    #pragma unroll 4
    for (int k = 0; k < HH; k++) {
        float4 wv = *(const float4*)&Ws[k * 128 + tx * 4];
        ull w0 = pack2(wv.x), w1 = pack2(wv.y), w2 = pack2(wv.z), w3 = pack2(wv.w);
        #pragma unroll
        for (int p = 0; p < 4; p++) {
            int pair = ty + 8 * p;
            ull ap = *(const ull*)&Ast[k * AST + 2 * pair];
            ffma2(acc[p][0], ap, w0);
            ffma2(acc[p][1], ap, w1);
            ffma2(acc[p][2], ap, w2);
            ffma2(acc[p][3], ap, w3);
        }
    }

    #pragma unroll
    for (int p = 0; p < 4; p++) {
        int n0 = nbase + 2 * (ty + 8 * p);
        if (n0 >= NN) continue;
        bool ok1 = (n0 + 1) < NN;
        #pragma unroll
        for (int c = 0; c < 4; c++) {
            float v0, v1;
            unpack2(acc[p][c], v0, v1);
            int col = tx * 4 + c;
            float* dst = (col < 64) ? &g_h[0] + n0 * 64 + col
                                    : &g_res[0] + n0 * 64 + (col - 64);
            dst[0] = v0;
            if (ok1) dst[64] = v1;
        }
    }
}

// ---------------- attention projections: as/ad = h @ a ----------------------
__global__ void attn_proj(const float* __restrict__ av,
                          const float* __restrict__ adv) {
    int warp = (blockIdx.x * blockDim.x + threadIdx.x) >> 5;
    if (warp >= NN) return;
    int lane = threadIdx.x & 31;
    float h0 = g_h[warp * 64 + lane];
    float h1 = g_h[warp * 64 + 32 + lane];
    float sa = h0 * av[lane]  + h1 * av[lane + 32];
    float sd = h0 * adv[lane] + h1 * adv[lane + 32];
    #pragma unroll
    for (int off = 16; off > 0; off >>= 1) {
        sa += __shfl_xor_sync(0xffffffffu, sa, off);
        sd += __shfl_xor_sync(0xffffffffu, sd, off);
    }
    if (lane == 0) {
        g_as[warp] = sa;
        g_ad[warp] = sd;
    }
}

// ---------------- per-edge softmax weights (flat, max MLP) -------------------
__global__ void edge_w() {
    int i = blockIdx.x * blockDim.x + threadIdx.x;
    if (i >= ET) return;
    float e = g_as[g_csr_src[i]] + g_ad[g_csr_dst[i]];
    e = e > 0.f ? e : 0.2f * e;
    g_ew[i] = __expf(e);
}

// ---------------- fused GAT aggregation + epilogue ---------------------------
// One warp per destination node. csr_src + ew are streamed (L1 broadcast);
// only the h-row gathers are random, issued 4-deep for MLP.
template <int FIRST>
__global__ void gat_agg(const float* __restrict__ cb,
                        const float* __restrict__ pb,
                        const float* __restrict__ bg, const float* __restrict__ bb,
                        const float* __restrict__ bm, const float* __restrict__ bv) {
    int warp = (blockIdx.x * blockDim.x + threadIdx.x) >> 5;
    if (warp >= NN) return;
    int lane = threadIdx.x & 31;
    int beg = g_rowptr[warp];
    int end = g_rowptr[warp + 1];

    float s = 0.f;
    float2 acc = make_float2(0.f, 0.f);
    int j = beg;
    int fo = lane * 2;

    for (; j + 4 <= end; j += 4) {
        int s0 = g_csr_src[j];
        int s1 = g_csr_src[j + 1];
        int s2 = g_csr_src[j + 2];
        int s3 = g_csr_src[j + 3];
        float w0 = g_ew[j];
        float w1 = g_ew[j + 1];
        float w2 = g_ew[j + 2];
        float w3 = g_ew[j + 3];
        float2 h0 = *(const float2*)&g_h[s0 * 64 + fo];
        float2 h1 = *(const float2*)&g_h[s1 * 64 + fo];
        float2 h2 = *(const float2*)&g_h[s2 * 64 + fo];
        float2 h3 = *(const float2*)&g_h[s3 * 64 + fo];
        s += (w0 + w1) + (w2 + w3);
        acc.x += w0 * h0.x; acc.y += w0 * h0.y;
        acc.x += w1 * h1.x; acc.y += w1 * h1.y;
        acc.x += w2 * h2.x; acc.y += w2 * h2.y;
        acc.x += w3 * h3.x; acc.y += w3 * h3.y;
    }
    for (; j < end; j++) {
        int s0 = g_csr_src[j];
        float w0 = g_ew[j];
        float2 h0 = *(const float2*)&g_h[s0 * 64 + fo];
        s += w0;
        acc.x += w0 * h0.x;
        acc.y += w0 * h0.y;
    }

    float inv = 1.f / (s + 1e-16f);
    acc.x *= inv;
    acc.y *= inv;

    int f = fo;
    float v0 = fmaxf(acc.x + cb[f],     0.f);
    float v1 = fmaxf(acc.y + cb[f + 1], 0.f);
    v0 = (v0 - bm[f])     * rsqrtf(bv[f]     + 1e-5f) * bg[f]     + bb[f];
    v1 = (v1 - bm[f + 1]) * rsqrtf(bv[f + 1] + 1e-5f) * bg[f + 1] + bb[f + 1];
    if (!FIRST) {
        float2 rv = *(const float2*)&g_res[warp * 64 + f];
        v0 += rv.x + pb[f];
        v1 += rv.y + pb[f + 1];
    }
    *(float2*)&g_xp[warp * 64 + f] = make_float2(v0, v1);
}

// ---------------- pooling + head --------------------------------------------
__global__ void pool_zero() {
    if (threadIdx.x < HH) g_pool[threadIdx.x] = 0.f;
}

__global__ void pool_k() {
    __shared__ float sh[256];
    int t = threadIdx.x;
    int f = t & 63, g = t >> 6;
    float s = 0.f;
    for (int n = blockIdx.x * 4 + g; n < NN; n += 256 * 4)
        s += g_xp[n * 64 + f];
    sh[t] = s;
    __syncthreads();
    if (t < 64) {
        float tot = sh[t] + sh[t + 64] + sh[t + 128] + sh[t + 192];
        atomicAdd(&g_pool[f], tot);
    }
}

__global__ void head_k(const float* __restrict__ hW1, const float* __restrict__ hb1,
                       const float* __restrict__ hg, const float* __restrict__ hb,
                       const float* __restrict__ hm, const float* __restrict__ hv,
                       const float* __restrict__ hW2, const float* __restrict__ hb2,
                       float* __restrict__ out) {
    __shared__ float gs[64];
    __shared__ float hs[32];
    int t = threadIdx.x;
    if (t < 64) gs[t] = g_pool[t] * (1.0f / NN);
    __syncthreads();
    if (t < 32) {
        float acc = hb1[t];
        #pragma unroll 16
        for (int f = 0; f < 64; f++) acc += gs[f] * hW1[f * 32 + t];
        acc = fmaxf(acc, 0.f);
        acc = (acc - hm[t]) * rsqrtf(hv[t] + 1e-5f) * hg[t] + hb[t];
        hs[t] = acc * hW2[t];
    }
    __syncthreads();
    if (t == 0) {
        float s = 0.f;
        for (int j = 0; j < 32; j++) s += hs[j];
        out[0] = s + hb2[0];
    }
}

// ---------------- launch ----------------------------------------------------
extern "C" void kernel_launch(void* const* d_in, const int* in_sizes, int n_in,
                              void* d_out, int out_size) {
    const float* x        = (const float*)d_in[0];
    const int*   ei       = (const int*)d_in[1];
    const float* conv1_W  = (const float*)d_in[2];
    const float* conv1_as = (const float*)d_in[3];
    const float* conv1_ad = (const float*)d_in[4];
    const float* conv1_b  = (const float*)d_in[5];
    const float* convW    = (const float*)d_in[6];
    const float* conv_as  = (const float*)d_in[7];
    const float* conv_ad  = (const float*)d_in[8];
    const float* conv_b   = (const float*)d_in[9];
    const float* bn_g     = (const float*)d_in[10];
    const float* bn_b     = (const float*)d_in[11];
    const float* bn_m     = (const float*)d_in[12];
    const float* bn_v     = (const float*)d_in[13];
    const float* projW    = (const float*)d_in[14];
    const float* projb    = (const float*)d_in[15];
    const float* hW1      = (const float*)d_in[16];
    const float* hb1      = (const float*)d_in[17];
    const float* hbn_g    = (const float*)d_in[18];
    const float* hbn_b    = (const float*)d_in[19];
    const float* hbn_m    = (const float*)d_in[20];
    const float* hbn_v    = (const float*)d_in[21];
    const float* hW2      = (const float*)d_in[22];
    const float* hb2      = (const float*)d_in[23];
    float* out = (float*)d_out;

    const int NB_E    = (EE + 255) / 256;               // 3125
    const int NB_ET   = (ET + 255) / 256;
    const int NB_GEMM = (NN + 63) / 64;                 // 782
    const int NB_WARP = (NN * 32 + 255) / 256;          // 6250 (warp per node)

    const int SMEM_C1 = (KIN * 64 + KIN * 66) * 4;      // 66560 B
    const int SMEM_L  = (HH * 128 + HH * 66) * 4;       // 49664 B
    static int smem_set = 0;
    if (!smem_set) {
        cudaFuncSetAttribute(gemm_conv1, cudaFuncAttributeMaxDynamicSharedMemorySize, SMEM_C1);
        cudaFuncSetAttribute(gemm_layer, cudaFuncAttributeMaxDynamicSharedMemorySize, SMEM_L);
        smem_set = 1;
    }

    // ---- CSR build (once per launch, reused by all 5 layers) ----
    deg_init<<<(NN + 256) / 256, 256>>>();
    deg_count<<<NB_E, 256>>>(ei);
    scan_k<<<1, 1024>>>();
    cursor_init<<<(NN + 255) / 256, 256>>>();
    csr_fill<<<NB_E, 256>>>(ei);

    // ---- conv1 ----
    gemm_conv1<<<NB_GEMM, 128, SMEM_C1>>>(x, conv1_W);
    attn_proj<<<NB_WARP, 256>>>(conv1_as, conv1_ad);
    edge_w<<<NB_ET, 256>>>();
    gat_agg<1><<<NB_WARP, 256>>>(conv1_b, nullptr, bn_g, bn_b, bn_m, bn_v);

    // ---- conv2..conv5 ----
    for (int l = 0; l < 4; l++) {
        gemm_layer<<<NB_GEMM, 256, SMEM_L>>>(convW + l * 4096, projW + l * 4096);
        attn_proj<<<NB_WARP, 256>>>(conv_as + l * 64, conv_ad + l * 64);
        edge_w<<<NB_ET, 256>>>();
        gat_agg<0><<<NB_WARP, 256>>>(conv_b + l * 64, projb + l * 64,
                                     bn_g + (l + 1) * 64, bn_b + (l + 1) * 64,
                                     bn_m + (l + 1) * 64, bn_v + (l + 1) * 64);
    }

    // ---- pool + head ----
    pool_zero<<<1, 64>>>();
    pool_k<<<256, 256>>>();
    head_k<<<1, 64>>>(hW1, hb1, hbn_g, hbn_b, hbn_m, hbn_v, hW2, hb2, out);
}

// round 8
// speedup vs baseline: 2.0533x; 1.0440x over previous
#include <cuda_runtime.h>

#define NN 50000
#define EE 800000
#define HH 64
#define KIN 128
#define ET (EE + NN)

// ---------------- scratch (static __device__ globals; allocation-free) ------
__device__ __align__(16) float g_h[NN * HH];     // layer projection h
__device__ __align__(16) float g_xp[NN * HH];    // current node features
__device__ __align__(16) float g_res[NN * HH];   // residual projection
__device__ __align__(16) float g_as[NN];
__device__ __align__(16) float g_ad[NN];
__device__ __align__(16) float g_poolp[256 * HH];

// CSR scratch
__device__ int g_deg[NN + 1];
__device__ int g_rowptr[NN + 1];
__device__ int g_cursor[NN];
__device__ int g_csr_src[ET];

// ---------------- f32x2 packed helpers (sm_103a) -----------------------------
typedef unsigned long long ull;

__device__ __forceinline__ void ffma2(ull& d, ull a, ull b) {
    asm("fma.rn.f32x2 %0, %1, %2, %0;" : "+l"(d) : "l"(a), "l"(b));
}
__device__ __forceinline__ ull fadd2(ull a, ull b) {
    ull r;
    asm("add.rn.f32x2 %0, %1, %2;" : "=l"(r) : "l"(a), "l"(b));
    return r;
}
__device__ __forceinline__ ull pack2(float x) {
    ull r; unsigned u = __float_as_uint(x);
    asm("mov.b64 %0, {%1, %2};" : "=l"(r) : "r"(u), "r"(u));
    return r;
}
__device__ __forceinline__ void unpack2(ull v, float& lo, float& hi) {
    unsigned a, b;
    asm("mov.b64 {%0, %1}, %2;" : "=r"(a), "=r"(b) : "l"(v));
    lo = __uint_as_float(a); hi = __uint_as_float(b);
}

// ---------------- CSR build --------------------------------------------------
__global__ void deg_init() {
    int i = blockIdx.x * blockDim.x + threadIdx.x;
    if (i <= NN) g_deg[i] = (i < NN) ? 1 : 0;   // self-loop counted up front
}

__global__ void deg_count(const int* __restrict__ ei) {
    int i = blockIdx.x * blockDim.x + threadIdx.x;
    if (i >= EE) return;
    atomicAdd(&g_deg[ei[EE + i]], 1);
}

__global__ void scan_k() {
    __shared__ int part[1024];
    const int CH = 49;
    int t = threadIdx.x;
    int base = t * CH;
    int vals[CH];
    int s = 0;
    #pragma unroll
    for (int i = 0; i < CH; i++) {
        int idx = base + i;
        int v = (idx < NN) ? g_deg[idx] : 0;
        vals[i] = s;
        s += v;
    }
    part[t] = s;
    __syncthreads();
    for (int off = 1; off < 1024; off <<= 1) {
        int v = (t >= off) ? part[t - off] : 0;
        __syncthreads();
        part[t] += v;
        __syncthreads();
    }
    int prev = (t == 0) ? 0 : part[t - 1];
    #pragma unroll
    for (int i = 0; i < CH; i++) {
        int idx = base + i;
        if (idx <= NN) g_rowptr[idx] = prev + vals[i];
    }
}

__global__ void cursor_init() {
    int n = blockIdx.x * blockDim.x + threadIdx.x;
    if (n >= NN) return;
    int r = g_rowptr[n];
    g_csr_src[r] = n;                            // self loop first
    g_cursor[n] = r + 1;
}

__global__ void csr_fill(const int* __restrict__ ei) {
    int i = blockIdx.x * blockDim.x + threadIdx.x;
    if (i >= EE) return;
    int s = ei[i], d = ei[EE + i];
    int pos = atomicAdd(&g_cursor[d], 1);
    g_csr_src[pos] = s;
}

// ---------------- conv1 GEMM: x[N,128] x W[128,64] -> g_h, g_as, g_ad --------
// 64 nodes/block, 128 threads (tx=16 colgroups, ty=8 -> 4 node-pairs each).
// Attention projections fused into epilogue via half-warp shuffle reduce.
__global__ void gemm_conv1(const float* __restrict__ A,
                           const float* __restrict__ W,
                           const float* __restrict__ av,
                           const float* __restrict__ adv) {
    extern __shared__ float sm[];
    float* Ws  = sm;                 // [128][64]
    float* Ast = sm + KIN * 64;      // [128][66]
    const int AST = 66;

    int tid = threadIdx.x;
    int tx = tid & 15;
    int ty = tid >> 4;

    for (int i = tid; i < KIN * 64; i += 128) Ws[i] = W[i];
    int nbase = blockIdx.x * 64;
    for (int i = tid; i < 64 * KIN; i += 128) {
        int node = i / KIN, k = i % KIN;
        int n = nbase + node;
        Ast[k * AST + node] = (n < NN) ? A[n * KIN + k] : 0.f;
    }
    __syncthreads();

    ull acc[4][4];
    #pragma unroll
    for (int p = 0; p < 4; p++)
        #pragma unroll
        for (int c = 0; c < 4; c++) acc[p][c] = 0ull;

    #pragma unroll 4
    for (int k = 0; k < KIN; k++) {
        float4 wv = *(const float4*)&Ws[k * 64 + tx * 4];
        ull w0 = pack2(wv.x), w1 = pack2(wv.y), w2 = pack2(wv.z), w3 = pack2(wv.w);
        #pragma unroll
        for (int p = 0; p < 4; p++) {
            int pair = ty + 8 * p;
            ull ap = *(const ull*)&Ast[k * AST + 2 * pair];
            ffma2(acc[p][0], ap, w0);
            ffma2(acc[p][1], ap, w1);
            ffma2(acc[p][2], ap, w2);
            ffma2(acc[p][3], ap, w3);
        }
    }

    // epilogue: store h + fused attention projections
    float4 a4  = *(const float4*)&av[tx * 4];
    float4 ad4 = *(const float4*)&adv[tx * 4];
    #pragma unroll
    for (int p = 0; p < 4; p++) {
        int n0 = nbase + 2 * (ty + 8 * p);
        bool ok0 = n0 < NN;
        bool ok1 = (n0 + 1) < NN;
        #pragma unroll
        for (int c = 0; c < 4; c++) {
            float v0, v1;
            unpack2(acc[p][c], v0, v1);
            int col = tx * 4 + c;
            if (ok0) g_h[n0 * 64 + col] = v0;
            if (ok1) g_h[(n0 + 1) * 64 + col] = v1;
        }
        // partial as/ad for this node pair (packed)
        ull pa = 0ull, pd = 0ull;
        ffma2(pa, acc[p][0], pack2(a4.x));  ffma2(pa, acc[p][1], pack2(a4.y));
        ffma2(pa, acc[p][2], pack2(a4.z));  ffma2(pa, acc[p][3], pack2(a4.w));
        ffma2(pd, acc[p][0], pack2(ad4.x)); ffma2(pd, acc[p][1], pack2(ad4.y));
        ffma2(pd, acc[p][2], pack2(ad4.z)); ffma2(pd, acc[p][3], pack2(ad4.w));
        #pragma unroll
        for (int off = 8; off > 0; off >>= 1) {
            pa = fadd2(pa, __shfl_xor_sync(0xffffffffu, pa, off));
            pd = fadd2(pd, __shfl_xor_sync(0xffffffffu, pd, off));
        }
        if (tx == 0) {
            float a0, a1, d0, d1;
            unpack2(pa, a0, a1);
            unpack2(pd, d0, d1);
            if (ok0) { g_as[n0] = a0; g_ad[n0] = d0; }
            if (ok1) { g_as[n0 + 1] = a1; g_ad[n0 + 1] = d1; }
        }
    }
}

// ---------------- layer GEMM: g_xp[N,64] x [convW|projW][64,128] -------------
// 64 nodes/block, 256 threads (tx=32 colgroups; tx<16 = conv cols -> h,
// tx>=16 = proj cols -> res). Attention projections fused (reduce over tx<16).
__global__ void gemm_layer(const float* __restrict__ CW,
                           const float* __restrict__ PW,
                           const float* __restrict__ av,
                           const float* __restrict__ adv) {
    extern __shared__ float sm[];
    float* Ws  = sm;                 // [64][128]
    float* Ast = sm + HH * 128;      // [64][66]
    const int AST = 66;

    int tid = threadIdx.x;
    int tx = tid & 31;
    int ty = tid >> 5;

    for (int i = tid; i < HH * 128; i += 256) {
        int k = i >> 7, c = i & 127;
        Ws[i] = (c < 64) ? CW[k * 64 + c] : PW[k * 64 + (c - 64)];
    }
    int nbase = blockIdx.x * 64;
    for (int i = tid; i < 64 * HH; i += 256) {
        int node = i >> 6, k = i & 63;
        int n = nbase + node;
        Ast[k * AST + node] = (n < NN) ? g_xp[n * 64 + k] : 0.f;
    }
    __syncthreads();

    ull acc[4][4];
    #pragma unroll
    for (int p = 0; p < 4; p++)
        #pragma unroll
        for (int c = 0; c < 4; c++) acc[p][c] = 0ull;

    #pragma unroll 4
    for (int k = 0; k < HH; k++) {
        float4 wv = *(const float4*)&Ws[k * 128 + tx * 4];
        ull w0 = pack2(wv.x), w1 = pack2(wv.y), w2 = pack2(wv.z), w3 = pack2(wv.w);
        #pragma unroll
        for (int p = 0; p < 4; p++) {
            int pair = ty + 8 * p;
            ull ap = *(const ull*)&Ast[k * AST + 2 * pair];
            ffma2(acc[p][0], ap, w0);
            ffma2(acc[p][1], ap, w1);
            ffma2(acc[p][2], ap, w2);
            ffma2(acc[p][3], ap, w3);
        }
    }

    bool is_h = (tx < 16);
    float4 a4  = make_float4(0.f, 0.f, 0.f, 0.f);
    float4 ad4 = make_float4(0.f, 0.f, 0.f, 0.f);
    if (is_h) {
        a4  = *(const float4*)&av[tx * 4];
        ad4 = *(const float4*)&adv[tx * 4];
    }
    #pragma unroll
    for (int p = 0; p < 4; p++) {
        int n0 = nbase + 2 * (ty + 8 * p);
        bool ok0 = n0 < NN;
        bool ok1 = (n0 + 1) < NN;
        #pragma unroll
        for (int c = 0; c < 4; c++) {
            float v0, v1;
            unpack2(acc[p][c], v0, v1);
            int col = tx * 4 + c;
            float* dst = is_h ? &g_h[0] + n0 * 64 + col
                              : &g_res[0] + n0 * 64 + (col - 64);
            if (ok0) dst[0] = v0;
            if (ok1) dst[64] = v1;
        }
        ull pa = 0ull, pd = 0ull;
        if (is_h) {
            ffma2(pa, acc[p][0], pack2(a4.x));  ffma2(pa, acc[p][1], pack2(a4.y));
            ffma2(pa, acc[p][2], pack2(a4.z));  ffma2(pa, acc[p][3], pack2(a4.w));
            ffma2(pd, acc[p][0], pack2(ad4.x)); ffma2(pd, acc[p][1], pack2(ad4.y));
            ffma2(pd, acc[p][2], pack2(ad4.z)); ffma2(pd, acc[p][3], pack2(ad4.w));
        }
        #pragma unroll
        for (int off = 16; off > 0; off >>= 1) {
            pa = fadd2(pa, __shfl_xor_sync(0xffffffffu, pa, off));
            pd = fadd2(pd, __shfl_xor_sync(0xffffffffu, pd, off));
        }
        if (tx == 0) {
            float a0, a1, d0, d1;
            unpack2(pa, a0, a1);
            unpack2(pd, d0, d1);
            if (ok0) { g_as[n0] = a0; g_ad[n0] = d0; }
            if (ok1) { g_as[n0 + 1] = a1; g_ad[n0 + 1] = d1; }
        }
    }
}

// ---------------- fused GAT: edge weights + aggregation + epilogue -----------
// One warp per destination node; softmax weight computed inline (the 4
// as-gathers per unroll step are independent -> MLP preserved).
template <int FIRST>
__global__ void gat_agg(const float* __restrict__ cb,
                        const float* __restrict__ pb,
                        const float* __restrict__ bg, const float* __restrict__ bb,
                        const float* __restrict__ bm, const float* __restrict__ bv) {
    int warp = (blockIdx.x * blockDim.x + threadIdx.x) >> 5;
    if (warp >= NN) return;
    int lane = threadIdx.x & 31;
    int beg = g_rowptr[warp];
    int end = g_rowptr[warp + 1];
    float adv = g_ad[warp];

    float s = 0.f;
    float2 acc = make_float2(0.f, 0.f);
    int j = beg;
    int fo = lane * 2;

    for (; j + 4 <= end; j += 4) {
        int s0 = g_csr_src[j];
        int s1 = g_csr_src[j + 1];
        int s2 = g_csr_src[j + 2];
        int s3 = g_csr_src[j + 3];
        float a0 = g_as[s0];
        float a1 = g_as[s1];
        float a2 = g_as[s2];
        float a3 = g_as[s3];
        float2 h0 = *(const float2*)&g_h[s0 * 64 + fo];
        float2 h1 = *(const float2*)&g_h[s1 * 64 + fo];
        float2 h2 = *(const float2*)&g_h[s2 * 64 + fo];
        float2 h3 = *(const float2*)&g_h[s3 * 64 + fo];
        float e0 = a0 + adv; e0 = e0 > 0.f ? e0 : 0.2f * e0;
        float e1 = a1 + adv; e1 = e1 > 0.f ? e1 : 0.2f * e1;
        float e2 = a2 + adv; e2 = e2 > 0.f ? e2 : 0.2f * e2;
        float e3 = a3 + adv; e3 = e3 > 0.f ? e3 : 0.2f * e3;
        float w0 = __expf(e0);
        float w1 = __expf(e1);
        float w2 = __expf(e2);
        float w3 = __expf(e3);
        s += (w0 + w1) + (w2 + w3);
        acc.x += w0 * h0.x; acc.y += w0 * h0.y;
        acc.x += w1 * h1.x; acc.y += w1 * h1.y;
        acc.x += w2 * h2.x; acc.y += w2 * h2.y;
        acc.x += w3 * h3.x; acc.y += w3 * h3.y;
    }
    for (; j < end; j++) {
        int s0 = g_csr_src[j];
        float e0 = g_as[s0] + adv; e0 = e0 > 0.f ? e0 : 0.2f * e0;
        float w0 = __expf(e0);
        float2 h0 = *(const float2*)&g_h[s0 * 64 + fo];
        s += w0;
        acc.x += w0 * h0.x;
        acc.y += w0 * h0.y;
    }

    float inv = 1.f / (s + 1e-16f);
    acc.x *= inv;
    acc.y *= inv;

    int f = fo;
    float v0 = fmaxf(acc.x + cb[f],     0.f);
    float v1 = fmaxf(acc.y + cb[f + 1], 0.f);
    v0 = (v0 - bm[f])     * rsqrtf(bv[f]     + 1e-5f) * bg[f]     + bb[f];
    v1 = (v1 - bm[f + 1]) * rsqrtf(bv[f + 1] + 1e-5f) * bg[f + 1] + bb[f + 1];
    if (!FIRST) {
        float2 rv = *(const float2*)&g_res[warp * 64 + f];
        v0 += rv.x + pb[f];
        v1 += rv.y + pb[f + 1];
    }
    *(float2*)&g_xp[warp * 64 + f] = make_float2(v0, v1);
}

// ---------------- pooling + head --------------------------------------------
__global__ void pool_k() {
    __shared__ float sh[256];
    int t = threadIdx.x;
    int f = t & 63, g = t >> 6;
    float s = 0.f;
    for (int n = blockIdx.x * 4 + g; n < NN; n += 256 * 4)
        s += g_xp[n * 64 + f];
    sh[t] = s;
    __syncthreads();
    if (t < 64)
        g_poolp[blockIdx.x * 64 + t] = sh[t] + sh[t + 64] + sh[t + 128] + sh[t + 192];
}

__global__ void head_k(const float* __restrict__ hW1, const float* __restrict__ hb1,
                       const float* __restrict__ hg, const float* __restrict__ hb,
                       const float* __restrict__ hm, const float* __restrict__ hv,
                       const float* __restrict__ hW2, const float* __restrict__ hb2,
                       float* __restrict__ out) {
    __shared__ float gs[64];
    __shared__ float hs[32];
    int t = threadIdx.x;
    if (t < 64) {
        float s = 0.f;
        for (int b = 0; b < 256; b++) s += g_poolp[b * 64 + t];
        gs[t] = s * (1.0f / NN);
    }
    __syncthreads();
    if (t < 32) {
        float acc = hb1[t];
        #pragma unroll 16
        for (int f = 0; f < 64; f++) acc += gs[f] * hW1[f * 32 + t];
        acc = fmaxf(acc, 0.f);
        acc = (acc - hm[t]) * rsqrtf(hv[t] + 1e-5f) * hg[t] + hb[t];
        hs[t] = acc * hW2[t];
    }
    __syncthreads();
    if (t == 0) {
        float s = 0.f;
        for (int j = 0; j < 32; j++) s += hs[j];
        out[0] = s + hb2[0];
    }
}

// ---------------- launch ----------------------------------------------------
extern "C" void kernel_launch(void* const* d_in, const int* in_sizes, int n_in,
                              void* d_out, int out_size) {
    const float* x        = (const float*)d_in[0];
    const int*   ei       = (const int*)d_in[1];
    const float* conv1_W  = (const float*)d_in[2];
    const float* conv1_as = (const float*)d_in[3];
    const float* conv1_ad = (const float*)d_in[4];
    const float* conv1_b  = (const float*)d_in[5];
    const float* convW    = (const float*)d_in[6];
    const float* conv_as  = (const float*)d_in[7];
    const float* conv_ad  = (const float*)d_in[8];
    const float* conv_b   = (const float*)d_in[9];
    const float* bn_g     = (const float*)d_in[10];
    const float* bn_b     = (const float*)d_in[11];
    const float* bn_m     = (const float*)d_in[12];
    const float* bn_v     = (const float*)d_in[13];
    const float* projW    = (const float*)d_in[14];
    const float* projb    = (const float*)d_in[15];
    const float* hW1      = (const float*)d_in[16];
    const float* hb1      = (const float*)d_in[17];
    const float* hbn_g    = (const float*)d_in[18];
    const float* hbn_b    = (const float*)d_in[19];
    const float* hbn_m    = (const float*)d_in[20];
    const float* hbn_v    = (const float*)d_in[21];
    const float* hW2      = (const float*)d_in[22];
    const float* hb2      = (const float*)d_in[23];
    float* out = (float*)d_out;

    const int NB_E    = (EE + 255) / 256;               // 3125
    const int NB_GEMM = (NN + 63) / 64;                 // 782
    const int NB_WARP = (NN * 32 + 255) / 256;          // 6250 (warp per node)

    const int SMEM_C1 = (KIN * 64 + KIN * 66) * 4;      // 66560 B
    const int SMEM_L  = (HH * 128 + HH * 66) * 4;       // 49664 B
    static int smem_set = 0;
    if (!smem_set) {
        cudaFuncSetAttribute(gemm_conv1, cudaFuncAttributeMaxDynamicSharedMemorySize, SMEM_C1);
        cudaFuncSetAttribute(gemm_layer, cudaFuncAttributeMaxDynamicSharedMemorySize, SMEM_L);
        smem_set = 1;
    }

    // ---- CSR build (once per launch, reused by all 5 layers) ----
    deg_init<<<(NN + 256) / 256, 256>>>();
    deg_count<<<NB_E, 256>>>(ei);
    scan_k<<<1, 1024>>>();
    cursor_init<<<(NN + 255) / 256, 256>>>();
    csr_fill<<<NB_E, 256>>>(ei);

    // ---- conv1 ----
    gemm_conv1<<<NB_GEMM, 128, SMEM_C1>>>(x, conv1_W, conv1_as, conv1_ad);
    gat_agg<1><<<NB_WARP, 256>>>(conv1_b, nullptr, bn_g, bn_b, bn_m, bn_v);

    // ---- conv2..conv5 ----
    for (int l = 0; l < 4; l++) {
        gemm_layer<<<NB_GEMM, 256, SMEM_L>>>(convW + l * 4096, projW + l * 4096,
                                             conv_as + l * 64, conv_ad + l * 64);
        gat_agg<0><<<NB_WARP, 256>>>(conv_b + l * 64, projb + l * 64,
                                     bn_g + (l + 1) * 64, bn_b + (l + 1) * 64,
                                     bn_m + (l + 1) * 64, bn_v + (l + 1) * 64);
    }

    // ---- pool + head ----
    pool_k<<<256, 256>>>();
    head_k<<<1, 64>>>(hW1, hb1, hbn_g, hbn_b, hbn_m, hbn_v, hW2, hb2, out);
}

// round 11
// speedup vs baseline: 2.1624x; 1.0531x over previous
#include <cuda_runtime.h>

#define NN 50000
#define EE 800000
#define HH 64
#define KIN 128
#define ET (EE + NN)
#define NSCAN_BLK 196                 // 196*256 = 50176 >= NN+1

// ---------------- scratch (static __device__ globals; allocation-free) ------
__device__ __align__(16) float g_h[NN * HH];     // layer projection h
__device__ __align__(16) float g_xp[NN * HH];    // current node features
__device__ __align__(16) float g_res[NN * HH];   // residual projection
__device__ __align__(16) float g_as[NN];
__device__ __align__(16) float g_ad[NN];
__device__ __align__(16) float g_poolp[6250 * HH];

// CSR scratch
__device__ int g_deg[NN + 1];
__device__ int g_rowptr[NN + 1];
__device__ int g_cursor[NN];
__device__ int g_csr_src[ET];
__device__ int g_btot[NSCAN_BLK];
__device__ int g_boff[NSCAN_BLK];

// ---------------- f32x2 packed helpers (sm_103a) -----------------------------
typedef unsigned long long ull;

__device__ __forceinline__ void ffma2(ull& d, ull a, ull b) {
    asm("fma.rn.f32x2 %0, %1, %2, %0;" : "+l"(d) : "l"(a), "l"(b));
}
__device__ __forceinline__ ull fadd2(ull a, ull b) {
    ull r;
    asm("add.rn.f32x2 %0, %1, %2;" : "=l"(r) : "l"(a), "l"(b));
    return r;
}
__device__ __forceinline__ ull pack2(float x) {
    ull r; unsigned u = __float_as_uint(x);
    asm("mov.b64 %0, {%1, %2};" : "=l"(r) : "r"(u), "r"(u));
    return r;
}
__device__ __forceinline__ void unpack2(ull v, float& lo, float& hi) {
    unsigned a, b;
    asm("mov.b64 {%0, %1}, %2;" : "=r"(a), "=r"(b) : "l"(v));
    lo = __uint_as_float(a); hi = __uint_as_float(b);
}

// ---------------- CSR build --------------------------------------------------
__global__ void deg_init() {
    int i = blockIdx.x * blockDim.x + threadIdx.x;
    if (i <= NN) g_deg[i] = (i < NN) ? 1 : 0;   // self-loop counted up front
}

__global__ void deg_count(const int* __restrict__ ei) {
    int i = blockIdx.x * blockDim.x + threadIdx.x;
    if (i >= EE) return;
    atomicAdd(&g_deg[ei[EE + i]], 1);
}

// phase 1: per-block exclusive scan (coalesced loads, shfl scans)
__global__ void scan_local() {
    __shared__ int wsum[8];
    int t = threadIdx.x;
    int idx = blockIdx.x * 256 + t;
    int d = (idx < NN) ? g_deg[idx] : 0;
    int v = d;
    #pragma unroll
    for (int o = 1; o < 32; o <<= 1) {
        int u = __shfl_up_sync(0xffffffffu, v, o);
        if ((t & 31) >= o) v += u;
    }
    if ((t & 31) == 31) wsum[t >> 5] = v;
    __syncthreads();
    if (t < 32) {
        int w = (t < 8) ? wsum[t] : 0;
        #pragma unroll
        for (int o = 1; o < 8; o <<= 1) {
            int u = __shfl_up_sync(0xffffffffu, w, o);
            if (t >= o) w += u;
        }
        if (t < 8) wsum[t] = w;          // inclusive warp totals
    }
    __syncthreads();
    int excl = v - d + ((t >> 5) ? wsum[(t >> 5) - 1] : 0);
    if (idx <= NN) g_rowptr[idx] = excl;
    if (t == 255) g_btot[blockIdx.x] = wsum[7];
}

// phase 2: single-block exclusive scan of the 196 block totals
__global__ void scan_tot() {
    __shared__ int wsum[8];
    int t = threadIdx.x;
    int d = (t < NSCAN_BLK) ? g_btot[t] : 0;
    int v = d;
    #pragma unroll
    for (int o = 1; o < 32; o <<= 1) {
        int u = __shfl_up_sync(0xffffffffu, v, o);
        if ((t & 31) >= o) v += u;
    }
    if ((t & 31) == 31) wsum[t >> 5] = v;
    __syncthreads();
    if (t < 32) {
        int w = (t < 8) ? wsum[t] : 0;
        #pragma unroll
        for (int o = 1; o < 8; o <<= 1) {
            int u = __shfl_up_sync(0xffffffffu, w, o);
            if (t >= o) w += u;
        }
        if (t < 8) wsum[t] = w;
    }
    __syncthreads();
    int excl = v - d + ((t >> 5) ? wsum[(t >> 5) - 1] : 0);
    if (t < NSCAN_BLK) g_boff[t] = excl;
}

// phase 3: add block offsets + (fused) cursor/self-loop init
__global__ void scan_add() {
    int t = threadIdx.x;
    int idx = blockIdx.x * 256 + t;
    if (idx > NN) return;
    int r = g_rowptr[idx] + g_boff[blockIdx.x];
    g_rowptr[idx] = r;
    if (idx < NN) {
        g_csr_src[r] = idx;              // self loop first
        g_cursor[idx] = r + 1;
    }
}

__global__ void csr_fill(const int* __restrict__ ei) {
    int i = blockIdx.x * blockDim.x + threadIdx.x;
    if (i >= EE) return;
    int s = ei[i], d = ei[EE + i];
    int pos = atomicAdd(&g_cursor[d], 1);
    g_csr_src[pos] = s;
}

// ---------------- conv1 GEMM: x[N,128] x W[128,64] -> g_h, g_as, g_ad --------
__global__ void gemm_conv1(const float* __restrict__ A,
                           const float* __restrict__ W,
                           const float* __restrict__ av,
                           const float* __restrict__ adv) {
    extern __shared__ float sm[];
    float* Ws  = sm;                 // [128][64]
    float* Ast = sm + KIN * 64;      // [128][66]
    const int AST = 66;

    int tid = threadIdx.x;
    int tx = tid & 15;
    int ty = tid >> 4;

    for (int i = tid; i < KIN * 64; i += 128) Ws[i] = W[i];
    int nbase = blockIdx.x * 64;
    for (int i = tid; i < 64 * KIN; i += 128) {
        int node = i / KIN, k = i % KIN;
        int n = nbase + node;
        Ast[k * AST + node] = (n < NN) ? A[n * KIN + k] : 0.f;
    }
    __syncthreads();

    ull acc[4][4];
    #pragma unroll
    for (int p = 0; p < 4; p++)
        #pragma unroll
        for (int c = 0; c < 4; c++) acc[p][c] = 0ull;

    #pragma unroll 4
    for (int k = 0; k < KIN; k++) {
        float4 wv = *(const float4*)&Ws[k * 64 + tx * 4];
        ull w0 = pack2(wv.x), w1 = pack2(wv.y), w2 = pack2(wv.z), w3 = pack2(wv.w);
        #pragma unroll
        for (int p = 0; p < 4; p++) {
            int pair = ty + 8 * p;
            ull ap = *(const ull*)&Ast[k * AST + 2 * pair];
            ffma2(acc[p][0], ap, w0);
            ffma2(acc[p][1], ap, w1);
            ffma2(acc[p][2], ap, w2);
            ffma2(acc[p][3], ap, w3);
        }
    }

    float4 a4  = *(const float4*)&av[tx * 4];
    float4 ad4 = *(const float4*)&adv[tx * 4];
    #pragma unroll
    for (int p = 0; p < 4; p++) {
        int n0 = nbase + 2 * (ty + 8 * p);
        bool ok0 = n0 < NN;
        bool ok1 = (n0 + 1) < NN;
        #pragma unroll
        for (int c = 0; c < 4; c++) {
            float v0, v1;
            unpack2(acc[p][c], v0, v1);
            int col = tx * 4 + c;
            if (ok0) g_h[n0 * 64 + col] = v0;
            if (ok1) g_h[(n0 + 1) * 64 + col] = v1;
        }
        ull pa = 0ull, pd = 0ull;
        ffma2(pa, acc[p][0], pack2(a4.x));  ffma2(pa, acc[p][1], pack2(a4.y));
        ffma2(pa, acc[p][2], pack2(a4.z));  ffma2(pa, acc[p][3], pack2(a4.w));
        ffma2(pd, acc[p][0], pack2(ad4.x)); ffma2(pd, acc[p][1], pack2(ad4.y));
        ffma2(pd, acc[p][2], pack2(ad4.z)); ffma2(pd, acc[p][3], pack2(ad4.w));
        #pragma unroll
        for (int off = 8; off > 0; off >>= 1) {
            pa = fadd2(pa, __shfl_xor_sync(0xffffffffu, pa, off));
            pd = fadd2(pd, __shfl_xor_sync(0xffffffffu, pd, off));
        }
        if (tx == 0) {
            float a0, a1, d0, d1;
            unpack2(pa, a0, a1);
            unpack2(pd, d0, d1);
            if (ok0) { g_as[n0] = a0; g_ad[n0] = d0; }
            if (ok1) { g_as[n0 + 1] = a1; g_ad[n0 + 1] = d1; }
        }
    }
}

// ---------------- layer GEMM: g_xp[N,64] x [convW|projW][64,128] -------------
__global__ void gemm_layer(const float* __restrict__ CW,
                           const float* __restrict__ PW,
                           const float* __restrict__ av,
                           const float* __restrict__ adv) {
    extern __shared__ float sm[];
    float* Ws  = sm;                 // [64][128]
    float* Ast = sm + HH * 128;      // [64][66]
    const int AST = 66;

    int tid = threadIdx.x;
    int tx = tid & 31;
    int ty = tid >> 5;

    for (int i = tid; i < HH * 128; i += 256) {
        int k = i >> 7, c = i & 127;
        Ws[i] = (c < 64) ? CW[k * 64 + c] : PW[k * 64 + (c - 64)];
    }
    int nbase = blockIdx.x * 64;
    for (int i = tid; i < 64 * HH; i += 256) {
        int node = i >> 6, k = i & 63;
        int n = nbase + node;
        Ast[k * AST + node] = (n < NN) ? g_xp[n * 64 + k] : 0.f;
    }
    __syncthreads();

    ull acc[4][4];
    #pragma unroll
    for (int p = 0; p < 4; p++)
        #pragma unroll
        for (int c = 0; c < 4; c++) acc[p][c] = 0ull;

    #pragma unroll 4
    for (int k = 0; k < HH; k++) {
        float4 wv = *(const float4*)&Ws[k * 128 + tx * 4];
        ull w0 = pack2(wv.x), w1 = pack2(wv.y), w2 = pack2(wv.z), w3 = pack2(wv.w);
        #pragma unroll
        for (int p = 0; p < 4; p++) {
            int pair = ty + 8 * p;
            ull ap = *(const ull*)&Ast[k * AST + 2 * pair];
            ffma2(acc[p][0], ap, w0);
            ffma2(acc[p][1], ap, w1);
            ffma2(acc[p][2], ap, w2);
            ffma2(acc[p][3], ap, w3);
        }
    }

    bool is_h = (tx < 16);
    float4 a4  = make_float4(0.f, 0.f, 0.f, 0.f);
    float4 ad4 = make_float4(0.f, 0.f, 0.f, 0.f);
    if (is_h) {
        a4  = *(const float4*)&av[tx * 4];
        ad4 = *(const float4*)&adv[tx * 4];
    }
    #pragma unroll
    for (int p = 0; p < 4; p++) {
        int n0 = nbase + 2 * (ty + 8 * p);
        bool ok0 = n0 < NN;
        bool ok1 = (n0 + 1) < NN;
        #pragma unroll
        for (int c = 0; c < 4; c++) {
            float v0, v1;
            unpack2(acc[p][c], v0, v1);
            int col = tx * 4 + c;
            float* dst = is_h ? &g_h[0] + n0 * 64 + col
                              : &g_res[0] + n0 * 64 + (col - 64);
            if (ok0) dst[0] = v0;
            if (ok1) dst[64] = v1;
        }
        ull pa = 0ull, pd = 0ull;
        if (is_h) {
            ffma2(pa, acc[p][0], pack2(a4.x));  ffma2(pa, acc[p][1], pack2(a4.y));
            ffma2(pa, acc[p][2], pack2(a4.z));  ffma2(pa, acc[p][3], pack2(a4.w));
            ffma2(pd, acc[p][0], pack2(ad4.x)); ffma2(pd, acc[p][1], pack2(ad4.y));
            ffma2(pd, acc[p][2], pack2(ad4.z)); ffma2(pd, acc[p][3], pack2(ad4.w));
        }
        #pragma unroll
        for (int off = 16; off > 0; off >>= 1) {
            pa = fadd2(pa, __shfl_xor_sync(0xffffffffu, pa, off));
            pd = fadd2(pd, __shfl_xor_sync(0xffffffffu, pd, off));
        }
        if (tx == 0) {
            float a0, a1, d0, d1;
            unpack2(pa, a0, a1);
            unpack2(pd, d0, d1);
            if (ok0) { g_as[n0] = a0; g_ad[n0] = d0; }
            if (ok1) { g_as[n0 + 1] = a1; g_ad[n0 + 1] = d1; }
        }
    }
}

// ---------------- fused GAT: edge weights + aggregation + epilogue -----------
// One warp per destination node; 6250 blocks x 8 warps == 50000 nodes exactly.
// POOL: also reduce this block's 8 xp rows into g_poolp[block].
template <int FIRST, int POOL>
__global__ void gat_agg(const float* __restrict__ cb,
                        const float* __restrict__ pb,
                        const float* __restrict__ bg, const float* __restrict__ bb,
                        const float* __restrict__ bm, const float* __restrict__ bv) {
    __shared__ float sp[POOL ? 512 : 1];
    int warp = (blockIdx.x * blockDim.x + threadIdx.x) >> 5;
    int lane = threadIdx.x & 31;
    int beg = g_rowptr[warp];
    int end = g_rowptr[warp + 1];
    float adv = g_ad[warp];

    float s = 0.f;
    float2 acc = make_float2(0.f, 0.f);
    int j = beg;
    int fo = lane * 2;

    for (; j + 4 <= end; j += 4) {
        int s0 = g_csr_src[j];
        int s1 = g_csr_src[j + 1];
        int s2 = g_csr_src[j + 2];
        int s3 = g_csr_src[j + 3];
        float a0 = g_as[s0];
        float a1 = g_as[s1];
        float a2 = g_as[s2];
        float a3 = g_as[s3];
        float2 h0 = *(const float2*)&g_h[s0 * 64 + fo];
        float2 h1 = *(const float2*)&g_h[s1 * 64 + fo];
        float2 h2 = *(const float2*)&g_h[s2 * 64 + fo];
        float2 h3 = *(const float2*)&g_h[s3 * 64 + fo];
        float e0 = a0 + adv; e0 = e0 > 0.f ? e0 : 0.2f * e0;
        float e1 = a1 + adv; e1 = e1 > 0.f ? e1 : 0.2f * e1;
        float e2 = a2 + adv; e2 = e2 > 0.f ? e2 : 0.2f * e2;
        float e3 = a3 + adv; e3 = e3 > 0.f ? e3 : 0.2f * e3;
        float w0 = __expf(e0);
        float w1 = __expf(e1);
        float w2 = __expf(e2);
        float w3 = __expf(e3);
        s += (w0 + w1) + (w2 + w3);
        acc.x += w0 * h0.x; acc.y += w0 * h0.y;
        acc.x += w1 * h1.x; acc.y += w1 * h1.y;
        acc.x += w2 * h2.x; acc.y += w2 * h2.y;
        acc.x += w3 * h3.x; acc.y += w3 * h3.y;
    }
    for (; j < end; j++) {
        int s0 = g_csr_src[j];
        float e0 = g_as[s0] + adv; e0 = e0 > 0.f ? e0 : 0.2f * e0;
        float w0 = __expf(e0);
        float2 h0 = *(const float2*)&g_h[s0 * 64 + fo];
        s += w0;
        acc.x += w0 * h0.x;
        acc.y += w0 * h0.y;
    }

    float inv = 1.f / (s + 1e-16f);
    acc.x *= inv;
    acc.y *= inv;

    int f = fo;
    float v0 = fmaxf(acc.x + cb[f],     0.f);
    float v1 = fmaxf(acc.y + cb[f + 1], 0.f);
    v0 = (v0 - bm[f])     * rsqrtf(bv[f]     + 1e-5f) * bg[f]     + bb[f];
    v1 = (v1 - bm[f + 1]) * rsqrtf(bv[f + 1] + 1e-5f) * bg[f + 1] + bb[f + 1];
    if (!FIRST) {
        float2 rv = *(const float2*)&g_res[warp * 64 + f];
        v0 += rv.x + pb[f];
        v1 += rv.y + pb[f + 1];
    }
    *(float2*)&g_xp[warp * 64 + f] = make_float2(v0, v1);

    if (POOL) {
        int w = threadIdx.x >> 5;
        sp[w * 64 + f] = v0;
        sp[w * 64 + f + 1] = v1;
        __syncthreads();
        int t = threadIdx.x;
        if (t < 64) {
            float ps = 0.f;
            #pragma unroll
            for (int k = 0; k < 8; k++) ps += sp[k * 64 + t];
            g_poolp[blockIdx.x * 64 + t] = ps;
        }
    }
}

// ---------------- head: sum pool partials + MLP ------------------------------
__global__ void head_k(const float* __restrict__ hW1, const float* __restrict__ hb1,
                       const float* __restrict__ hg, const float* __restrict__ hb,
                       const float* __restrict__ hm, const float* __restrict__ hv,
                       const float* __restrict__ hW2, const float* __restrict__ hb2,
                       float* __restrict__ out) {
    __shared__ float part[512];
    __shared__ float gs[64];
    __shared__ float hs[32];
    int t = threadIdx.x;
    int f = t & 63, g = t >> 6;              // 8 batches
    float s = 0.f;
    for (int b = g; b < 6250; b += 8)
        s += g_poolp[b * 64 + f];
    part[t] = s;
    __syncthreads();
    if (t < 64) {
        float tot = 0.f;
        #pragma unroll
        for (int k = 0; k < 8; k++) tot += part[k * 64 + t];
        gs[t] = tot * (1.0f / NN);
    }
    __syncthreads();
    if (t < 32) {
        float acc = hb1[t];
        #pragma unroll 16
        for (int ff = 0; ff < 64; ff++) acc += gs[ff] * hW1[ff * 32 + t];
        acc = fmaxf(acc, 0.f);
        acc = (acc - hm[t]) * rsqrtf(hv[t] + 1e-5f) * hg[t] + hb[t];
        hs[t] = acc * hW2[t];
    }
    __syncthreads();
    if (t == 0) {
        float ss = 0.f;
        for (int j = 0; j < 32; j++) ss += hs[j];
        out[0] = ss + hb2[0];
    }
}

// ---------------- launch ----------------------------------------------------
extern "C" void kernel_launch(void* const* d_in, const int* in_sizes, int n_in,
                              void* d_out, int out_size) {
    const float* x        = (const float*)d_in[0];
    const int*   ei       = (const int*)d_in[1];
    const float* conv1_W  = (const float*)d_in[2];
    const float* conv1_as = (const float*)d_in[3];
    const float* conv1_ad = (const float*)d_in[4];
    const float* conv1_b  = (const float*)d_in[5];
    const float* convW    = (const float*)d_in[6];
    const float* conv_as  = (const float*)d_in[7];
    const float* conv_ad  = (const float*)d_in[8];
    const float* conv_b   = (const float*)d_in[9];
    const float* bn_g     = (const float*)d_in[10];
    const float* bn_b     = (const float*)d_in[11];
    const float* bn_m     = (const float*)d_in[12];
    const float* bn_v     = (const float*)d_in[13];
    const float* projW    = (const float*)d_in[14];
    const float* projb    = (const float*)d_in[15];
    const float* hW1      = (const float*)d_in[16];
    const float* hb1      = (const float*)d_in[17];
    const float* hbn_g    = (const float*)d_in[18];
    const float* hbn_b    = (const float*)d_in[19];
    const float* hbn_m    = (const float*)d_in[20];
    const float* hbn_v    = (const float*)d_in[21];
    const float* hW2      = (const float*)d_in[22];
    const float* hb2      = (const float*)d_in[23];
    float* out = (float*)d_out;

    const int NB_E    = (EE + 255) / 256;               // 3125
    const int NB_GEMM = (NN + 63) / 64;                 // 782
    const int NB_WARP = (NN * 32) / 256;                // 6250 (warp per node)

    const int SMEM_C1 = (KIN * 64 + KIN * 66) * 4;      // 66560 B
    const int SMEM_L  = (HH * 128 + HH * 66) * 4;       // 49664 B
    static int smem_set = 0;
    if (!smem_set) {
        cudaFuncSetAttribute(gemm_conv1, cudaFuncAttributeMaxDynamicSharedMemorySize, SMEM_C1);
        cudaFuncSetAttribute(gemm_layer, cudaFuncAttributeMaxDynamicSharedMemorySize, SMEM_L);
        smem_set = 1;
    }

    // ---- CSR build (once per launch, reused by all 5 layers) ----
    deg_init<<<(NN + 256) / 256, 256>>>();
    deg_count<<<NB_E, 256>>>(ei);
    scan_local<<<NSCAN_BLK, 256>>>();
    scan_tot<<<1, 256>>>();
    scan_add<<<NSCAN_BLK, 256>>>();
    csr_fill<<<NB_E, 256>>>(ei);

    // ---- conv1 ----
    gemm_conv1<<<NB_GEMM, 128, SMEM_C1>>>(x, conv1_W, conv1_as, conv1_ad);
    gat_agg<1, 0><<<NB_WARP, 256>>>(conv1_b, nullptr, bn_g, bn_b, bn_m, bn_v);

    // ---- conv2..conv5 (pool fused into last agg) ----
    for (int l = 0; l < 4; l++) {
        gemm_layer<<<NB_GEMM, 256, SMEM_L>>>(convW + l * 4096, projW + l * 4096,
                                             conv_as + l * 64, conv_ad + l * 64);
        if (l < 3)
            gat_agg<0, 0><<<NB_WARP, 256>>>(conv_b + l * 64, projb + l * 64,
                                            bn_g + (l + 1) * 64, bn_b + (l + 1) * 64,
                                            bn_m + (l + 1) * 64, bn_v + (l + 1) * 64);
        else
            gat_agg<0, 1><<<NB_WARP, 256>>>(conv_b + l * 64, projb + l * 64,
                                            bn_g + (l + 1) * 64, bn_b + (l + 1) * 64,
                                            bn_m + (l + 1) * 64, bn_v + (l + 1) * 64);
    }

    // ---- head ----
    head_k<<<1, 512>>>(hW1, hb1, hbn_g, hbn_b, hbn_m, hbn_v, hW2, hb2, out);
}